// round 6
// baseline (speedup 1.0000x reference)
#include <cuda_runtime.h>
#include <cstdint>
#include <math.h>

#define NB   8
#define LATD 128
#define HD   1024
#define KD   294
#define ND   100000
#define ED   1600000

// ---------------- scratch (device globals; no allocation allowed) ----------
__device__ __align__(16) float g_hT0[HD * NB];   // [j][b]
__device__ __align__(16) float g_hT1[HD * NB];
__device__ __align__(16) float g_cbuf[KD * 24];  // [k][j], j = b*3+axis (x64 scaled)
__device__ __align__(16) float g_f[(size_t)ND * 24];   // [n][b*3+axis]
__device__ __align__(16) float g_fb[(size_t)ND * 24];
__device__ __align__(16) float g_sinv[ND];
__device__ float g_regsum;
__device__ int   g_is64;
// CSR
__device__ int  g_count[ND];
__device__ int  g_rowptr[ND + 1];
__device__ int  g_cursor[ND];
__device__ __align__(8) int2 g_recs[ED];         // {src, bitcast(w)} sorted by dst

// ---------------- edge_index dtype detection --------------------------------
__global__ void k_detect(const int* __restrict__ ei32) {
    __shared__ int any_nonzero;
    int t = threadIdx.x;
    if (t == 0) any_nonzero = 0;
    __syncthreads();
    int v = ei32[2 * (t * 64) + 1];
    if (v != 0) atomicOr(&any_nonzero, 1);
    __syncthreads();
    if (t == 0) g_is64 = (any_nonzero == 0) ? 1 : 0;
}

__device__ __forceinline__ int load_ei(const int* __restrict__ ei32, size_t pos) {
    return g_is64 ? ei32[2 * pos] : ei32[pos];
}

// ---------------- MLP: one thread per (j, b), coalesced W ------------------
__global__ void k_mlp0(const float* __restrict__ latent,
                       const float* __restrict__ W0,
                       const float* __restrict__ b0) {
    int j = blockIdx.x * 256 + threadIdx.x;     // grid (HD/256, NB)
    int b = blockIdx.y;
    const float* lp = latent + b * LATD;
    const float* Wp = W0 + j;
    float acc = 0.f;
#pragma unroll 8
    for (int i = 0; i < LATD; i++)
        acc += lp[i] * Wp[(size_t)i * HD];
    g_hT0[j * NB + b] = fmaxf(acc + b0[j], 0.f);
}

__global__ void k_layer(const float* __restrict__ hin,
                        float* __restrict__ hout,
                        const float* __restrict__ W,
                        const float* __restrict__ bias) {
    int j = blockIdx.x * 256 + threadIdx.x;     // grid (HD/256, NB)
    int b = blockIdx.y;
    const float* Wp = W + j;
    float acc = 0.f;
#pragma unroll 8
    for (int i = 0; i < HD; i++)
        acc += hin[i * NB + b] * Wp[(size_t)i * HD];
    float v = hin[j * NB + b] + acc + bias[j];
    hout[j * NB + b] = fmaxf(v, 0.f);
}

// coeff heads fused with epilogue: cbuf (x64) + regsum
__global__ void k_coeff(const float* __restrict__ h,
                        const float* __restrict__ Wx,
                        const float* __restrict__ bx,
                        const float* __restrict__ Wy,
                        const float* __restrict__ by,
                        const float* __restrict__ Wz,
                        const float* __restrict__ bz) {
    int k = threadIdx.x;                        // block 320, grid (3, NB)
    int axis = blockIdx.x;
    int b = blockIdx.y;
    const float* W = (axis == 0) ? Wx : ((axis == 1) ? Wy : Wz);
    const float* bias = (axis == 0) ? bx : ((axis == 1) ? by : bz);
    float ss = 0.f;
    if (k < KD) {
        const float* Wp = W + k;
        float acc = 0.f;
#pragma unroll 8
        for (int i = 0; i < HD; i++)
            acc += h[i * NB + b] * Wp[(size_t)i * KD];
        float v = acc + bias[k];
        g_cbuf[k * 24 + b * 3 + axis] = 64.f * v;
        ss = v * v;
    }
    // warp-reduce then one atomic per warp
#pragma unroll
    for (int off = 16; off > 0; off >>= 1)
        ss += __shfl_down_sync(0xFFFFFFFFu, ss, off);
    if ((threadIdx.x & 31) == 0 && ss != 0.f) atomicAdd(&g_regsum, ss);
}

// -------- big GEMM: f[n][j] = sum_k cbuf[k][j] * Z[k][n] --------------------
__global__ __launch_bounds__(64) void k_gemm(const float* __restrict__ Z) {
    __shared__ __align__(16) float4 cs[KD * 6];
    int tid = threadIdx.x;
    const float4* cb4 = (const float4*)g_cbuf;
    for (int t = tid; t < KD * 6; t += 64) cs[t] = cb4[t];
    __syncthreads();
    int n = blockIdx.x * 256 + tid * 4;
    if (n >= ND) return;
    float acc[96];
#pragma unroll
    for (int t = 0; t < 96; t++) acc[t] = 0.f;
    const float4* Zp = (const float4*)Z + (n >> 2);
    for (int k = 0; k < KD; k++) {
        float4 z = Zp[(size_t)k * (ND / 4)];
        float zz[4] = {z.x, z.y, z.z, z.w};
        const float4* cr = &cs[k * 6];
#pragma unroll
        for (int q = 0; q < 6; q++) {
            float4 c = cr[q];
            float cc[4] = {c.x, c.y, c.z, c.w};
#pragma unroll
            for (int t = 0; t < 4; t++)
#pragma unroll
                for (int comp = 0; comp < 4; comp++)
                    acc[(q * 4 + t) * 4 + comp] += cc[t] * zz[comp];
        }
    }
#pragma unroll
    for (int comp = 0; comp < 4; comp++) {
        float4* out = (float4*)(g_f + (size_t)(n + comp) * 24);
#pragma unroll
        for (int q = 0; q < 6; q++) {
            out[q] = make_float4(acc[(q * 4 + 0) * 4 + comp],
                                 acc[(q * 4 + 1) * 4 + comp],
                                 acc[(q * 4 + 2) * 4 + comp],
                                 acc[(q * 4 + 3) * 4 + comp]);
        }
    }
}

// ---------------- CSR build -------------------------------------------------
__global__ void k_hist(const int* __restrict__ ei32) {
    int e = blockIdx.x * 256 + threadIdx.x;
    if (e >= ED) return;
    int d = load_ei(ei32, (size_t)ED + e);
    if ((unsigned)d >= ND) return;
    atomicAdd(&g_count[d], 1);
}

__global__ void k_scan() {
    __shared__ int sp[1024];
    int t = threadIdx.x;
    const int CH = (ND + 1023) / 1024;
    int base = t * CH;
    int sum = 0;
    for (int i = 0; i < CH; i++) {
        int idx = base + i;
        if (idx < ND) sum += g_count[idx];
    }
    sp[t] = sum;
    __syncthreads();
    for (int off = 1; off < 1024; off <<= 1) {
        int v = (t >= off) ? sp[t - off] : 0;
        __syncthreads();
        sp[t] += v;
        __syncthreads();
    }
    int run = (t == 0) ? 0 : sp[t - 1];
    for (int i = 0; i < CH; i++) {
        int idx = base + i;
        if (idx < ND) {
            g_rowptr[idx] = run;
            g_cursor[idx] = run;
            run += g_count[idx];
        }
    }
    if (t == 1023) g_rowptr[ND] = sp[1023];
}

__global__ void k_fill(const int* __restrict__ ei32,
                       const float* __restrict__ ew) {
    int e = blockIdx.x * 256 + threadIdx.x;
    if (e >= ED) return;
    int s = load_ei(ei32, (size_t)e);
    int d = load_ei(ei32, (size_t)ED + e);
    if ((unsigned)s >= ND || (unsigned)d >= ND) return;
    int slot = atomicAdd(&g_cursor[d], 1);
    g_recs[slot] = make_int2(s, __float_as_int(ew[e]));
}

// ---------------- diffusion step: gather + fused combine --------------------
template <bool FIRST>
__global__ void k_gather(const float* __restrict__ fin,
                         float* __restrict__ fout) {
    int n = blockIdx.x * 256 + threadIdx.x;
    if (n >= ND) return;
    int beg = g_rowptr[n];
    int end = g_rowptr[n + 1];
    float acc[24];
#pragma unroll
    for (int t = 0; t < 24; t++) acc[t] = 0.f;
    float wsum = 0.f;
    for (int i = beg; i < end; i++) {
        int2 r = g_recs[i];
        int src = r.x;
        float w = __int_as_float(r.y);
        if (FIRST) wsum += w;
        const float4* fs = (const float4*)(fin + (size_t)src * 24);
#pragma unroll
        for (int q = 0; q < 6; q++) {
            float4 m = fs[q];
            acc[q * 4 + 0] += m.x * w;
            acc[q * 4 + 1] += m.y * w;
            acc[q * 4 + 2] += m.z * w;
            acc[q * 4 + 3] += m.w * w;
        }
    }
    float sinv;
    if (FIRST) {
        sinv = 0.5f / fmaxf(wsum, 1e-6f);
        g_sinv[n] = sinv;
    } else {
        sinv = g_sinv[n];
    }
    const float4* f0 = (const float4*)(fin + (size_t)n * 24);
    float4* fo = (float4*)(fout + (size_t)n * 24);
#pragma unroll
    for (int q = 0; q < 6; q++) {
        float4 f = f0[q];
        fo[q] = make_float4(0.5f * f.x + acc[q * 4 + 0] * sinv,
                            0.5f * f.y + acc[q * 4 + 1] * sinv,
                            0.5f * f.z + acc[q * 4 + 2] * sinv,
                            0.5f * f.w + acc[q * 4 + 3] * sinv);
    }
}

// -------- output transpose [n][b][axis] -> [b][n][axis] ---------------------
__global__ void k_output(const float* __restrict__ f, float* __restrict__ out) {
    int g = blockIdx.x * 256 + threadIdx.x;
    if (g >= NB * ND) return;
    int b = g / ND;
    int n = g - b * ND;
    const float* fp = f + (size_t)n * 24 + b * 3;
    float* op = out + (size_t)b * (ND * 3) + (size_t)n * 3;
    op[0] = fp[0]; op[1] = fp[1]; op[2] = fp[2];
}

__global__ void k_reg(float* __restrict__ out, int do_write) {
    if (do_write) out[(size_t)NB * ND * 3] = 1e-4f * sqrtf(g_regsum);
}

// ---------------------------------------------------------------------------
extern "C" void kernel_launch(void* const* d_in, const int* in_sizes, int n_in,
                              void* d_out, int out_size) {
    const float* latent = (const float*)d_in[0];
    const float* W0 = (const float*)d_in[1];
    const float* b0 = (const float*)d_in[2];
    const float* W1 = (const float*)d_in[3];
    const float* b1 = (const float*)d_in[4];
    const float* W2 = (const float*)d_in[5];
    const float* b2 = (const float*)d_in[6];
    const float* W3 = (const float*)d_in[7];
    const float* b3 = (const float*)d_in[8];
    const float* Wx = (const float*)d_in[9];
    const float* bx = (const float*)d_in[10];
    const float* Wy = (const float*)d_in[11];
    const float* by = (const float*)d_in[12];
    const float* Wz = (const float*)d_in[13];
    const float* bz = (const float*)d_in[14];
    const float* Z  = (const float*)d_in[15];
    const float* ew = (const float*)d_in[16];
    const int*   ei = (const int*)d_in[17];   // int32 OR int64 (auto-detected)
    float* out = (float*)d_out;

    void *p_f, *p_fb, *p_reg, *p_count, *p_h0, *p_h1;
    cudaGetSymbolAddress(&p_f, g_f);
    cudaGetSymbolAddress(&p_fb, g_fb);
    cudaGetSymbolAddress(&p_reg, g_regsum);
    cudaGetSymbolAddress(&p_count, g_count);
    cudaGetSymbolAddress(&p_h0, g_hT0);
    cudaGetSymbolAddress(&p_h1, g_hT1);

    cudaMemsetAsync(p_reg, 0, sizeof(float));
    cudaMemsetAsync(p_count, 0, (size_t)ND * sizeof(int));

    k_detect<<<1, 256>>>(ei);

    // CSR build (independent of MLP; interleave to fill the chip)
    k_hist<<<(ED + 255) / 256, 256>>>(ei);

    // MLP decode
    k_mlp0<<<dim3(HD / 256, NB), 256>>>(latent, W0, b0);
    k_layer<<<dim3(HD / 256, NB), 256>>>((float*)p_h0, (float*)p_h1, W1, b1);
    k_layer<<<dim3(HD / 256, NB), 256>>>((float*)p_h1, (float*)p_h0, W2, b2);
    k_layer<<<dim3(HD / 256, NB), 256>>>((float*)p_h0, (float*)p_h1, W3, b3);
    k_coeff<<<dim3(3, NB), 320>>>((float*)p_h1, Wx, bx, Wy, by, Wz, bz);

    k_scan<<<1, 1024>>>();
    k_fill<<<(ED + 255) / 256, 256>>>(ei, ew);

    // dense projection onto basis Z
    k_gemm<<<(ND + 255) / 256, 64>>>(Z);

    // diffusion: 3 gather steps, combine fused, deg computed in step 1
    k_gather<true ><<<(ND + 255) / 256, 256>>>((float*)p_f,  (float*)p_fb);
    k_gather<false><<<(ND + 255) / 256, 256>>>((float*)p_fb, (float*)p_f);
    k_gather<false><<<(ND + 255) / 256, 256>>>((float*)p_f,  (float*)p_fb);

    // outputs
    k_output<<<(NB * ND + 255) / 256, 256>>>((float*)p_fb, out);
    k_reg<<<1, 1>>>(out, (out_size > NB * ND * 3) ? 1 : 0);
}

// round 8
// speedup vs baseline: 1.3660x; 1.3660x over previous
#include <cuda_runtime.h>
#include <cstdint>
#include <math.h>

#define NB   8
#define LATD 128
#define HD   1024
#define KD   294
#define ND   100000
#define ED   1600000
#define NCH  8          // split-K chunks for MLP layers

// ---------------- scratch (device globals; no allocation allowed) ----------
__device__ __align__(16) float g_hT0[HD * NB];            // [j][b]
__device__ __align__(16) float g_hT1[HD * NB];
__device__ __align__(16) float g_part[NCH * HD * NB];     // layer partials
__device__ __align__(16) float g_cpart[3 * NCH * KD * NB];
__device__ __align__(16) float2 g_cbuf2[KD * 24];         // duplicated (c,c), x64
__device__ __align__(16) float g_f[(size_t)ND * 24];      // [n][b*3+axis]
__device__ __align__(16) float g_fb[(size_t)ND * 24];
__device__ float g_regsum;
__device__ int   g_is64;
// CSR
__device__ int   g_count[ND];
__device__ float g_wdeg[ND];
__device__ int   g_rowptr[ND + 1];
__device__ int   g_cursor[ND];
__device__ __align__(8) int2 g_recs[ED];   // {src*24, bitcast(w')} grouped by dst

// ---------------- edge_index dtype detection --------------------------------
__global__ void k_detect(const int* __restrict__ ei32) {
    __shared__ int any_nonzero;
    int t = threadIdx.x;
    if (t == 0) any_nonzero = 0;
    __syncthreads();
    int v = ei32[2 * (t * 64) + 1];
    if (v != 0) atomicOr(&any_nonzero, 1);
    __syncthreads();
    if (t == 0) g_is64 = (any_nonzero == 0) ? 1 : 0;
}

__device__ __forceinline__ int load_ei(const int* __restrict__ ei32, size_t pos) {
    return g_is64 ? ei32[2 * pos] : ei32[pos];
}

// ---------------- layer 0: hT0[j][b] = relu(latent @ W0 + b0) ---------------
__global__ void k_mlp0(const float* __restrict__ latent,
                       const float* __restrict__ W0,
                       const float* __restrict__ b0) {
    __shared__ __align__(16) float slat[LATD * NB];   // [i][b]
    int tid = threadIdx.x;
    for (int idx = tid; idx < LATD * NB; idx += 128) {
        int i = idx & (LATD - 1);
        int b = idx >> 7;
        slat[i * NB + b] = latent[b * LATD + i];
    }
    __syncthreads();
    int j = blockIdx.x * 128 + tid;
    float acc[NB];
#pragma unroll
    for (int b = 0; b < NB; b++) acc[b] = 0.f;
    const float* Wp = W0 + j;
#pragma unroll 4
    for (int i = 0; i < LATD; i++) {
        float w = Wp[(size_t)i * HD];
        const float4* h4 = (const float4*)&slat[i * NB];
        float4 a = h4[0], c = h4[1];
        acc[0] += a.x * w; acc[1] += a.y * w; acc[2] += a.z * w; acc[3] += a.w * w;
        acc[4] += c.x * w; acc[5] += c.y * w; acc[6] += c.z * w; acc[7] += c.w * w;
    }
    float bb = b0[j];
#pragma unroll
    for (int b = 0; b < NB; b++) g_hT0[j * NB + b] = fmaxf(acc[b] + bb, 0.f);
}

// -------- residual layer split-K: partials to g_part (no atomics) -----------
__global__ void k_layer_splitK(const float* __restrict__ hT,
                               const float* __restrict__ W) {
    __shared__ __align__(16) float sh[128 * NB];      // [ii][b]
    int tid = threadIdx.x;
    int ch = blockIdx.y;
    int i0 = ch * 128;
    const float4* src = (const float4*)(hT + (size_t)i0 * NB);
    float4* d4 = (float4*)sh;
    for (int t = tid; t < 256; t += 128) d4[t] = src[t];
    __syncthreads();
    int j = blockIdx.x * 128 + tid;
    float acc[NB];
#pragma unroll
    for (int b = 0; b < NB; b++) acc[b] = 0.f;
    const float* Wp = W + (size_t)i0 * HD + j;
#pragma unroll 4
    for (int ii = 0; ii < 128; ii++) {
        float w = Wp[(size_t)ii * HD];
        const float4* h4 = (const float4*)&sh[ii * NB];
        float4 a = h4[0], c = h4[1];
        acc[0] += a.x * w; acc[1] += a.y * w; acc[2] += a.z * w; acc[3] += a.w * w;
        acc[4] += c.x * w; acc[5] += c.y * w; acc[6] += c.z * w; acc[7] += c.w * w;
    }
    float4* dst = (float4*)&g_part[((size_t)ch * HD + j) * NB];
    dst[0] = make_float4(acc[0], acc[1], acc[2], acc[3]);
    dst[1] = make_float4(acc[4], acc[5], acc[6], acc[7]);
}

__global__ void k_layer_epi(const float* __restrict__ hT_in,
                            float* __restrict__ hT_out,
                            const float* __restrict__ bias) {
    int j = blockIdx.x * 128 + threadIdx.x;
    float bb = bias[j];
    float acc[NB];
#pragma unroll
    for (int b = 0; b < NB; b++) acc[b] = hT_in[j * NB + b] + bb;
#pragma unroll
    for (int c = 0; c < NCH; c++) {
        const float4* p = (const float4*)&g_part[((size_t)c * HD + j) * NB];
        float4 a = p[0], d = p[1];
        acc[0] += a.x; acc[1] += a.y; acc[2] += a.z; acc[3] += a.w;
        acc[4] += d.x; acc[5] += d.y; acc[6] += d.z; acc[7] += d.w;
    }
#pragma unroll
    for (int b = 0; b < NB; b++) hT_out[j * NB + b] = fmaxf(acc[b], 0.f);
}

// -------- coefficient heads split-K -----------------------------------------
__global__ void k_coeff_splitK(const float* __restrict__ hT,
                               const float* __restrict__ Wx,
                               const float* __restrict__ Wy,
                               const float* __restrict__ Wz) {
    __shared__ __align__(16) float sh[128 * NB];
    int tid = threadIdx.x;
    int ch = blockIdx.y;
    int i0 = ch * 128;
    const float4* src = (const float4*)(hT + (size_t)i0 * NB);
    float4* d4 = (float4*)sh;
    if (tid < 256) d4[tid] = src[tid];
    __syncthreads();
    int k = tid;
    if (k >= KD) return;
    int axis = blockIdx.x;
    const float* W = (axis == 0) ? Wx : ((axis == 1) ? Wy : Wz);
    const float* Wp = W + (size_t)i0 * KD + k;
    float acc[NB];
#pragma unroll
    for (int b = 0; b < NB; b++) acc[b] = 0.f;
#pragma unroll 4
    for (int ii = 0; ii < 128; ii++) {
        float w = Wp[(size_t)ii * KD];
        const float4* h4 = (const float4*)&sh[ii * NB];
        float4 a = h4[0], c = h4[1];
        acc[0] += a.x * w; acc[1] += a.y * w; acc[2] += a.z * w; acc[3] += a.w * w;
        acc[4] += c.x * w; acc[5] += c.y * w; acc[6] += c.z * w; acc[7] += c.w * w;
    }
    float4* dst = (float4*)&g_cpart[(((size_t)axis * NCH + ch) * KD + k) * NB];
    dst[0] = make_float4(acc[0], acc[1], acc[2], acc[3]);
    dst[1] = make_float4(acc[4], acc[5], acc[6], acc[7]);
}

// epi: reduce chunks, write duplicated x64 pairs to g_cbuf2, accumulate reg
__global__ void k_coeff_epi(const float* __restrict__ bx,
                            const float* __restrict__ by,
                            const float* __restrict__ bz) {
    int k = threadIdx.x;
    float ss = 0.f;
    if (k < KD) {
#pragma unroll
        for (int axis = 0; axis < 3; axis++) {
            const float* bias = (axis == 0) ? bx : ((axis == 1) ? by : bz);
            float bb = bias[k];
            float acc[NB];
#pragma unroll
            for (int b = 0; b < NB; b++) acc[b] = bb;
#pragma unroll
            for (int c = 0; c < NCH; c++) {
                const float4* p = (const float4*)&g_cpart[(((size_t)axis * NCH + c) * KD + k) * NB];
                float4 a = p[0], d = p[1];
                acc[0] += a.x; acc[1] += a.y; acc[2] += a.z; acc[3] += a.w;
                acc[4] += d.x; acc[5] += d.y; acc[6] += d.z; acc[7] += d.w;
            }
#pragma unroll
            for (int b = 0; b < NB; b++) {
                float v = acc[b];
                ss += v * v;
                float sv = 64.f * v;
                g_cbuf2[k * 24 + b * 3 + axis] = make_float2(sv, sv);
            }
        }
    }
#pragma unroll
    for (int off = 16; off > 0; off >>= 1)
        ss += __shfl_down_sync(0xFFFFFFFFu, ss, off);
    if ((threadIdx.x & 31) == 0) atomicAdd(&g_regsum, ss);
}

// -------- big GEMM with packed f32x2 FMA ------------------------------------
// f[n][j] = sum_k cbuf[k][j] * Z[k][n] ; c duplicated pairs, z natural pairs.
__global__ __launch_bounds__(64) void k_gemm(const float* __restrict__ Z) {
    extern __shared__ __align__(16) unsigned long long cs[];  // KD*24 u64 pairs
    int tid = threadIdx.x;
    const ulonglong2* src = (const ulonglong2*)g_cbuf2;
    ulonglong2* d2 = (ulonglong2*)cs;
    for (int t = tid; t < KD * 12; t += 64) d2[t] = src[t];
    __syncthreads();
    int n = blockIdx.x * 256 + tid * 4;
    if (n >= ND) return;
    unsigned long long acc2[48];                 // [j][p], p=0:(comp0,1) p=1:(comp2,3)
#pragma unroll
    for (int t = 0; t < 48; t++) acc2[t] = 0ULL;
    const ulonglong2* Zp = (const ulonglong2*)(Z + n);
    for (int k = 0; k < KD; k++) {
        ulonglong2 z = Zp[(size_t)k * (ND / 4)];
        unsigned long long zp0 = z.x, zp1 = z.y;
        const ulonglong2* cr = (const ulonglong2*)&cs[k * 24];
#pragma unroll
        for (int q = 0; q < 12; q++) {
            ulonglong2 c = cr[q];
            int j0 = q * 2;
            asm("fma.rn.f32x2 %0, %1, %2, %0;" : "+l"(acc2[j0 * 2 + 0]) : "l"(c.x), "l"(zp0));
            asm("fma.rn.f32x2 %0, %1, %2, %0;" : "+l"(acc2[j0 * 2 + 1]) : "l"(c.x), "l"(zp1));
            asm("fma.rn.f32x2 %0, %1, %2, %0;" : "+l"(acc2[j0 * 2 + 2]) : "l"(c.y), "l"(zp0));
            asm("fma.rn.f32x2 %0, %1, %2, %0;" : "+l"(acc2[j0 * 2 + 3]) : "l"(c.y), "l"(zp1));
        }
    }
    float vals[96];                              // [j][comp]
#pragma unroll
    for (int j = 0; j < 24; j++) {
#pragma unroll
        for (int p = 0; p < 2; p++) {
            float lo, hi;
            asm("mov.b64 {%0,%1}, %2;" : "=f"(lo), "=f"(hi) : "l"(acc2[j * 2 + p]));
            vals[j * 4 + 2 * p]     = lo;
            vals[j * 4 + 2 * p + 1] = hi;
        }
    }
#pragma unroll
    for (int comp = 0; comp < 4; comp++) {
        float4* out = (float4*)(g_f + (size_t)(n + comp) * 24);
#pragma unroll
        for (int q = 0; q < 6; q++)
            out[q] = make_float4(vals[(q * 4 + 0) * 4 + comp],
                                 vals[(q * 4 + 1) * 4 + comp],
                                 vals[(q * 4 + 2) * 4 + comp],
                                 vals[(q * 4 + 3) * 4 + comp]);
    }
}

// ---------------- CSR build -------------------------------------------------
__global__ void k_hist(const int* __restrict__ ei32,
                       const float* __restrict__ ew) {
    int e = blockIdx.x * 256 + threadIdx.x;
    if (e >= ED) return;
    int d = load_ei(ei32, (size_t)ED + e);
    if ((unsigned)d >= ND) return;
    atomicAdd(&g_count[d], 1);
    atomicAdd(&g_wdeg[d], ew[e]);
}

__global__ void k_scan() {
    __shared__ int sp[1024];
    int t = threadIdx.x;
    const int CH = (ND + 1023) / 1024;
    int base = t * CH;
    int sum = 0;
    for (int i = 0; i < CH; i++) {
        int idx = base + i;
        if (idx < ND) sum += g_count[idx];
    }
    sp[t] = sum;
    __syncthreads();
    for (int off = 1; off < 1024; off <<= 1) {
        int v = (t >= off) ? sp[t - off] : 0;
        __syncthreads();
        sp[t] += v;
        __syncthreads();
    }
    int run = (t == 0) ? 0 : sp[t - 1];
    for (int i = 0; i < CH; i++) {
        int idx = base + i;
        if (idx < ND) {
            g_rowptr[idx] = run;
            g_cursor[idx] = run;
            run += g_count[idx];
        }
    }
    if (t == 1023) g_rowptr[ND] = sp[1023];
}

__global__ void k_fill(const int* __restrict__ ei32,
                       const float* __restrict__ ew) {
    int e = blockIdx.x * 256 + threadIdx.x;
    if (e >= ED) return;
    int s = load_ei(ei32, (size_t)e);
    int d = load_ei(ei32, (size_t)ED + e);
    if ((unsigned)s >= ND || (unsigned)d >= ND) return;
    float wp = 0.5f * ew[e] / fmaxf(g_wdeg[d], 1e-6f);
    int slot = atomicAdd(&g_cursor[d], 1);
    g_recs[slot] = make_int2(s * 24, __float_as_int(wp));
}

// ---------------- diffusion: gather, combine fused, w' pre-normalized -------
__global__ void k_gather(const float* __restrict__ fin,
                         float* __restrict__ fout) {
    int n = blockIdx.x * 256 + threadIdx.x;
    if (n >= ND) return;
    int beg = g_rowptr[n];
    int end = g_rowptr[n + 1];
    float acc[24];
#pragma unroll
    for (int t = 0; t < 24; t++) acc[t] = 0.f;
    for (int i = beg; i < end; i++) {
        int2 r = g_recs[i];
        float w = __int_as_float(r.y);
        const float4* fs = (const float4*)(fin + r.x);
#pragma unroll
        for (int q = 0; q < 6; q++) {
            float4 m = fs[q];
            acc[q * 4 + 0] += m.x * w;
            acc[q * 4 + 1] += m.y * w;
            acc[q * 4 + 2] += m.z * w;
            acc[q * 4 + 3] += m.w * w;
        }
    }
    const float4* f0 = (const float4*)(fin + (size_t)n * 24);
    float4* fo = (float4*)(fout + (size_t)n * 24);
#pragma unroll
    for (int q = 0; q < 6; q++) {
        float4 f = f0[q];
        fo[q] = make_float4(0.5f * f.x + acc[q * 4 + 0],
                            0.5f * f.y + acc[q * 4 + 1],
                            0.5f * f.z + acc[q * 4 + 2],
                            0.5f * f.w + acc[q * 4 + 3]);
    }
}

// last step: gather + write directly to out in [b][n][3] layout
__global__ void k_gather_out(const float* __restrict__ fin,
                             float* __restrict__ out) {
    int n = blockIdx.x * 256 + threadIdx.x;
    if (n >= ND) return;
    int beg = g_rowptr[n];
    int end = g_rowptr[n + 1];
    float acc[24];
#pragma unroll
    for (int t = 0; t < 24; t++) acc[t] = 0.f;
    for (int i = beg; i < end; i++) {
        int2 r = g_recs[i];
        float w = __int_as_float(r.y);
        const float4* fs = (const float4*)(fin + r.x);
#pragma unroll
        for (int q = 0; q < 6; q++) {
            float4 m = fs[q];
            acc[q * 4 + 0] += m.x * w;
            acc[q * 4 + 1] += m.y * w;
            acc[q * 4 + 2] += m.z * w;
            acc[q * 4 + 3] += m.w * w;
        }
    }
    const float* f0 = fin + (size_t)n * 24;
#pragma unroll
    for (int b = 0; b < NB; b++) {
        float* op = out + (size_t)b * (ND * 3) + (size_t)n * 3;
#pragma unroll
        for (int a = 0; a < 3; a++)
            op[a] = 0.5f * f0[b * 3 + a] + acc[b * 3 + a];
    }
}

__global__ void k_reg(float* __restrict__ out, int do_write) {
    if (do_write) out[(size_t)NB * ND * 3] = 1e-4f * sqrtf(g_regsum);
}

// ---------------------------------------------------------------------------
extern "C" void kernel_launch(void* const* d_in, const int* in_sizes, int n_in,
                              void* d_out, int out_size) {
    const float* latent = (const float*)d_in[0];
    const float* W0 = (const float*)d_in[1];
    const float* b0 = (const float*)d_in[2];
    const float* W1 = (const float*)d_in[3];
    const float* b1 = (const float*)d_in[4];
    const float* W2 = (const float*)d_in[5];
    const float* b2 = (const float*)d_in[6];
    const float* W3 = (const float*)d_in[7];
    const float* b3 = (const float*)d_in[8];
    const float* Wx = (const float*)d_in[9];
    const float* bx = (const float*)d_in[10];
    const float* Wy = (const float*)d_in[11];
    const float* by = (const float*)d_in[12];
    const float* Wz = (const float*)d_in[13];
    const float* bz = (const float*)d_in[14];
    const float* Z  = (const float*)d_in[15];
    const float* ew = (const float*)d_in[16];
    const int*   ei = (const int*)d_in[17];   // int32 OR int64 (auto-detected)
    float* out = (float*)d_out;

    void *p_f, *p_fb, *p_reg, *p_count, *p_wdeg, *p_h0, *p_h1;
    cudaGetSymbolAddress(&p_f, g_f);
    cudaGetSymbolAddress(&p_fb, g_fb);
    cudaGetSymbolAddress(&p_reg, g_regsum);
    cudaGetSymbolAddress(&p_count, g_count);
    cudaGetSymbolAddress(&p_wdeg, g_wdeg);
    cudaGetSymbolAddress(&p_h0, g_hT0);
    cudaGetSymbolAddress(&p_h1, g_hT1);

    static int smem_set = 0;
    if (!smem_set) {
        cudaFuncSetAttribute(k_gemm, cudaFuncAttributeMaxDynamicSharedMemorySize,
                             KD * 24 * 8);
        smem_set = 1;
    }

    cudaMemsetAsync(p_reg, 0, sizeof(float));
    cudaMemsetAsync(p_count, 0, (size_t)ND * sizeof(int));
    cudaMemsetAsync(p_wdeg, 0, (size_t)ND * sizeof(float));

    k_detect<<<1, 256>>>(ei);
    k_hist<<<(ED + 255) / 256, 256>>>(ei, ew);

    // MLP decode (split-K, no atomics)
    k_mlp0<<<8, 128>>>(latent, W0, b0);
    k_layer_splitK<<<dim3(8, NCH), 128>>>((float*)p_h0, W1);
    k_layer_epi<<<8, 128>>>((float*)p_h0, (float*)p_h1, b1);
    k_layer_splitK<<<dim3(8, NCH), 128>>>((float*)p_h1, W2);
    k_layer_epi<<<8, 128>>>((float*)p_h1, (float*)p_h0, b2);
    k_layer_splitK<<<dim3(8, NCH), 128>>>((float*)p_h0, W3);
    k_layer_epi<<<8, 128>>>((float*)p_h0, (float*)p_h1, b3);
    k_coeff_splitK<<<dim3(3, NCH), 320>>>((float*)p_h1, Wx, Wy, Wz);
    k_coeff_epi<<<1, 320>>>(bx, by, bz);

    k_scan<<<1, 1024>>>();
    k_fill<<<(ED + 255) / 256, 256>>>(ei, ew);

    // dense projection onto basis Z (packed f32x2 FMA)
    k_gemm<<<(ND + 255) / 256, 64, KD * 24 * 8>>>(Z);

    // diffusion: 3 gather steps; last writes straight to out
    k_gather<<<(ND + 255) / 256, 256>>>((float*)p_f,  (float*)p_fb);
    k_gather<<<(ND + 255) / 256, 256>>>((float*)p_fb, (float*)p_f);
    k_gather_out<<<(ND + 255) / 256, 256>>>((float*)p_f, out);

    k_reg<<<1, 1>>>(out, (out_size > NB * ND * 3) ? 1 : 0);
}

// round 11
// speedup vs baseline: 2.2052x; 1.6143x over previous
#include <cuda_runtime.h>
#include <cstdint>
#include <math.h>

#define NB    8
#define LATD  128
#define HD    1024
#define KD    294
#define ND    100000
#define ED    1600000
#define NCH_L 16        // split-K chunks for residual layers (chunk = 64 rows)
#define NCH_0 4         // chunks for layer 0 (chunk = 32 rows)
#define NCH_C 16        // chunks for coeff heads (chunk = 64 rows)

// ---------------- scratch (device globals; no allocation allowed) ----------
__device__ __align__(16) float g_hT0[HD * NB];            // [j][b]
__device__ __align__(16) float g_hT1[HD * NB];
__device__ __align__(16) float g_part[NCH_L * HD * NB];   // layer partials [ch][j][b]
__device__ __align__(16) float g_cpart[3 * NCH_C * KD * NB];
__device__ __align__(16) float2 g_cbuf2[KD * 24];         // duplicated (c,c), x64
__device__ __align__(16) float g_f[(size_t)ND * 24];      // [n][b*3+axis]
__device__ __align__(16) float g_fb[(size_t)ND * 24];
__device__ float g_regsum;
__device__ int   g_is64;
// CSR
__device__ int   g_count[ND];
__device__ float g_wdeg[ND];
__device__ int   g_rowptr[ND + 1];
__device__ int   g_cursor[ND];
__device__ __align__(8) int2 g_recs[ED];   // {src*24, bitcast(w')} grouped by dst

// ---------------- edge_index dtype detection --------------------------------
__global__ void k_detect(const int* __restrict__ ei32) {
    __shared__ int any_nonzero;
    int t = threadIdx.x;
    if (t == 0) any_nonzero = 0;
    __syncthreads();
    int v = ei32[2 * (t * 64) + 1];
    if (v != 0) atomicOr(&any_nonzero, 1);
    __syncthreads();
    if (t == 0) g_is64 = (any_nonzero == 0) ? 1 : 0;
}

__device__ __forceinline__ int load_ei(const int* __restrict__ ei32, size_t pos) {
    return g_is64 ? ei32[2 * pos] : ei32[pos];
}

// ---------------- layer 0 split-K: chunk = 32 latent rows -------------------
__global__ void k_mlp0_splitK(const float* __restrict__ latent,
                              const float* __restrict__ W0) {
    __shared__ float slat[32 * NB];                   // [ii][b]
    int tid = threadIdx.x;
    int ch = blockIdx.y;
    int i0 = ch * 32;
    for (int idx = tid; idx < 32 * NB; idx += 128) {
        int ii = idx >> 3, b = idx & 7;
        slat[ii * NB + b] = latent[b * LATD + i0 + ii];
    }
    __syncthreads();
    int j = blockIdx.x * 128 + tid;
    float acc[NB];
#pragma unroll
    for (int b = 0; b < NB; b++) acc[b] = 0.f;
    const float* Wp = W0 + (size_t)i0 * HD + j;
#pragma unroll 8
    for (int ii = 0; ii < 32; ii++) {
        float w = Wp[(size_t)ii * HD];
        const float4* h4 = (const float4*)&slat[ii * NB];
        float4 a = h4[0], c = h4[1];
        acc[0] += a.x * w; acc[1] += a.y * w; acc[2] += a.z * w; acc[3] += a.w * w;
        acc[4] += c.x * w; acc[5] += c.y * w; acc[6] += c.z * w; acc[7] += c.w * w;
    }
    float4* dst = (float4*)&g_part[((size_t)ch * HD + j) * NB];
    dst[0] = make_float4(acc[0], acc[1], acc[2], acc[3]);
    dst[1] = make_float4(acc[4], acc[5], acc[6], acc[7]);
}

// -------- residual layer split-K: chunk = 64 rows ---------------------------
__global__ void k_layer_splitK(const float* __restrict__ hT,
                               const float* __restrict__ W) {
    __shared__ __align__(16) float sh[64 * NB];       // [ii][b]
    int tid = threadIdx.x;
    int ch = blockIdx.y;
    int i0 = ch * 64;
    const float4* src = (const float4*)(hT + (size_t)i0 * NB);
    ((float4*)sh)[tid] = src[tid];                    // 128 f4 = 64*8 floats
    __syncthreads();
    int j = blockIdx.x * 128 + tid;
    float acc[NB];
#pragma unroll
    for (int b = 0; b < NB; b++) acc[b] = 0.f;
    const float* Wp = W + (size_t)i0 * HD + j;
#pragma unroll 16
    for (int ii = 0; ii < 64; ii++) {
        float w = Wp[(size_t)ii * HD];
        const float4* h4 = (const float4*)&sh[ii * NB];
        float4 a = h4[0], c = h4[1];
        acc[0] += a.x * w; acc[1] += a.y * w; acc[2] += a.z * w; acc[3] += a.w * w;
        acc[4] += c.x * w; acc[5] += c.y * w; acc[6] += c.z * w; acc[7] += c.w * w;
    }
    float4* dst = (float4*)&g_part[((size_t)ch * HD + j) * NB];
    dst[0] = make_float4(acc[0], acc[1], acc[2], acc[3]);
    dst[1] = make_float4(acc[4], acc[5], acc[6], acc[7]);
}

// epilogue: reduce chunks (+bias, +optional residual), relu
template <int NCHUNKS, bool RES>
__global__ void k_epi(const float* __restrict__ hT_in,
                      float* __restrict__ hT_out,
                      const float* __restrict__ bias) {
    int j = blockIdx.x * 128 + threadIdx.x;
    float bb = bias[j];
    float acc[NB];
#pragma unroll
    for (int b = 0; b < NB; b++) acc[b] = RES ? (hT_in[j * NB + b] + bb) : bb;
#pragma unroll
    for (int c = 0; c < NCHUNKS; c++) {
        const float4* p = (const float4*)&g_part[((size_t)c * HD + j) * NB];
        float4 a = p[0], d = p[1];
        acc[0] += a.x; acc[1] += a.y; acc[2] += a.z; acc[3] += a.w;
        acc[4] += d.x; acc[5] += d.y; acc[6] += d.z; acc[7] += d.w;
    }
#pragma unroll
    for (int b = 0; b < NB; b++) hT_out[j * NB + b] = fmaxf(acc[b], 0.f);
}

// -------- coefficient heads split-K: chunk = 64 rows ------------------------
__global__ void k_coeff_splitK(const float* __restrict__ hT,
                               const float* __restrict__ Wx,
                               const float* __restrict__ Wy,
                               const float* __restrict__ Wz) {
    __shared__ __align__(16) float sh[64 * NB];
    int tid = threadIdx.x;
    int ch = blockIdx.y;
    int i0 = ch * 64;
    const float4* src = (const float4*)(hT + (size_t)i0 * NB);
    if (tid < 128) ((float4*)sh)[tid] = src[tid];
    __syncthreads();
    int k = tid;
    if (k >= KD) return;
    int axis = blockIdx.x;
    const float* W = (axis == 0) ? Wx : ((axis == 1) ? Wy : Wz);
    const float* Wp = W + (size_t)i0 * KD + k;
    float acc[NB];
#pragma unroll
    for (int b = 0; b < NB; b++) acc[b] = 0.f;
#pragma unroll 8
    for (int ii = 0; ii < 64; ii++) {
        float w = Wp[(size_t)ii * KD];
        const float4* h4 = (const float4*)&sh[ii * NB];
        float4 a = h4[0], c = h4[1];
        acc[0] += a.x * w; acc[1] += a.y * w; acc[2] += a.z * w; acc[3] += a.w * w;
        acc[4] += c.x * w; acc[5] += c.y * w; acc[6] += c.z * w; acc[7] += c.w * w;
    }
    float4* dst = (float4*)&g_cpart[(((size_t)axis * NCH_C + ch) * KD + k) * NB];
    dst[0] = make_float4(acc[0], acc[1], acc[2], acc[3]);
    dst[1] = make_float4(acc[4], acc[5], acc[6], acc[7]);
}

// epi: reduce chunks, write duplicated x64 pairs to g_cbuf2, accumulate reg
__global__ void k_coeff_epi(const float* __restrict__ bx,
                            const float* __restrict__ by,
                            const float* __restrict__ bz) {
    int k = threadIdx.x;
    float ss = 0.f;
    if (k < KD) {
#pragma unroll
        for (int axis = 0; axis < 3; axis++) {
            const float* bias = (axis == 0) ? bx : ((axis == 1) ? by : bz);
            float bb = bias[k];
            float acc[NB];
#pragma unroll
            for (int b = 0; b < NB; b++) acc[b] = bb;
#pragma unroll
            for (int c = 0; c < NCH_C; c++) {
                const float4* p = (const float4*)&g_cpart[(((size_t)axis * NCH_C + c) * KD + k) * NB];
                float4 a = p[0], d = p[1];
                acc[0] += a.x; acc[1] += a.y; acc[2] += a.z; acc[3] += a.w;
                acc[4] += d.x; acc[5] += d.y; acc[6] += d.z; acc[7] += d.w;
            }
#pragma unroll
            for (int b = 0; b < NB; b++) {
                float v = acc[b];
                ss += v * v;
                float sv = 64.f * v;
                g_cbuf2[k * 24 + b * 3 + axis] = make_float2(sv, sv);
            }
        }
    }
#pragma unroll
    for (int off = 16; off > 0; off >>= 1)
        ss += __shfl_down_sync(0xFFFFFFFFu, ss, off);
    if ((threadIdx.x & 31) == 0) atomicAdd(&g_regsum, ss);
}

// -------- big GEMM with packed f32x2 FMA ------------------------------------
__global__ __launch_bounds__(64) void k_gemm(const float* __restrict__ Z) {
    extern __shared__ __align__(16) unsigned long long cs[];  // KD*24 u64 pairs
    int tid = threadIdx.x;
    const ulonglong2* src = (const ulonglong2*)g_cbuf2;
    ulonglong2* d2 = (ulonglong2*)cs;
    for (int t = tid; t < KD * 12; t += 64) d2[t] = src[t];
    __syncthreads();
    int n = blockIdx.x * 256 + tid * 4;
    if (n >= ND) return;
    unsigned long long acc2[48];
#pragma unroll
    for (int t = 0; t < 48; t++) acc2[t] = 0ULL;
    const ulonglong2* Zp = (const ulonglong2*)(Z + n);
    for (int k = 0; k < KD; k++) {
        ulonglong2 z = Zp[(size_t)k * (ND / 4)];
        unsigned long long zp0 = z.x, zp1 = z.y;
        const ulonglong2* cr = (const ulonglong2*)&cs[k * 24];
#pragma unroll
        for (int q = 0; q < 12; q++) {
            ulonglong2 c = cr[q];
            int j0 = q * 2;
            asm("fma.rn.f32x2 %0, %1, %2, %0;" : "+l"(acc2[j0 * 2 + 0]) : "l"(c.x), "l"(zp0));
            asm("fma.rn.f32x2 %0, %1, %2, %0;" : "+l"(acc2[j0 * 2 + 1]) : "l"(c.x), "l"(zp1));
            asm("fma.rn.f32x2 %0, %1, %2, %0;" : "+l"(acc2[j0 * 2 + 2]) : "l"(c.y), "l"(zp0));
            asm("fma.rn.f32x2 %0, %1, %2, %0;" : "+l"(acc2[j0 * 2 + 3]) : "l"(c.y), "l"(zp1));
        }
    }
    float vals[96];
#pragma unroll
    for (int j = 0; j < 24; j++) {
#pragma unroll
        for (int p = 0; p < 2; p++) {
            float lo, hi;
            asm("mov.b64 {%0,%1}, %2;" : "=f"(lo), "=f"(hi) : "l"(acc2[j * 2 + p]));
            vals[j * 4 + 2 * p]     = lo;
            vals[j * 4 + 2 * p + 1] = hi;
        }
    }
#pragma unroll
    for (int comp = 0; comp < 4; comp++) {
        float4* out = (float4*)(g_f + (size_t)(n + comp) * 24);
#pragma unroll
        for (int q = 0; q < 6; q++)
            out[q] = make_float4(vals[(q * 4 + 0) * 4 + comp],
                                 vals[(q * 4 + 1) * 4 + comp],
                                 vals[(q * 4 + 2) * 4 + comp],
                                 vals[(q * 4 + 3) * 4 + comp]);
    }
}

// ---------------- CSR build -------------------------------------------------
__global__ void k_hist(const int* __restrict__ ei32,
                       const float* __restrict__ ew) {
    int e = blockIdx.x * 256 + threadIdx.x;
    if (e >= ED) return;
    int d = load_ei(ei32, (size_t)ED + e);
    if ((unsigned)d >= ND) return;
    atomicAdd(&g_count[d], 1);
    atomicAdd(&g_wdeg[d], ew[e]);
}

__global__ void k_scan() {
    __shared__ int sp[1024];
    int t = threadIdx.x;
    const int CH = (ND + 1023) / 1024;
    int base = t * CH;
    int sum = 0;
    for (int i = 0; i < CH; i++) {
        int idx = base + i;
        if (idx < ND) sum += g_count[idx];
    }
    sp[t] = sum;
    __syncthreads();
    for (int off = 1; off < 1024; off <<= 1) {
        int v = (t >= off) ? sp[t - off] : 0;
        __syncthreads();
        sp[t] += v;
        __syncthreads();
    }
    int run = (t == 0) ? 0 : sp[t - 1];
    for (int i = 0; i < CH; i++) {
        int idx = base + i;
        if (idx < ND) {
            g_rowptr[idx] = run;
            g_cursor[idx] = run;
            run += g_count[idx];
        }
    }
    if (t == 1023) g_rowptr[ND] = sp[1023];
}

__global__ void k_fill(const int* __restrict__ ei32,
                       const float* __restrict__ ew) {
    int e = blockIdx.x * 256 + threadIdx.x;
    if (e >= ED) return;
    int s = load_ei(ei32, (size_t)e);
    int d = load_ei(ei32, (size_t)ED + e);
    if ((unsigned)s >= ND || (unsigned)d >= ND) return;
    float wp = 0.5f * ew[e] / fmaxf(g_wdeg[d], 1e-6f);
    int slot = atomicAdd(&g_cursor[d], 1);
    g_recs[slot] = make_int2(s * 24, __float_as_int(wp));
}

// ---------------- diffusion: gather, combine fused, w' pre-normalized -------
__global__ void k_gather(const float* __restrict__ fin,
                         float* __restrict__ fout) {
    int n = blockIdx.x * 256 + threadIdx.x;
    if (n >= ND) return;
    int beg = g_rowptr[n];
    int end = g_rowptr[n + 1];
    float acc[24];
#pragma unroll
    for (int t = 0; t < 24; t++) acc[t] = 0.f;
    for (int i = beg; i < end; i++) {
        int2 r = g_recs[i];
        float w = __int_as_float(r.y);
        const float4* fs = (const float4*)(fin + r.x);
#pragma unroll
        for (int q = 0; q < 6; q++) {
            float4 m = fs[q];
            acc[q * 4 + 0] += m.x * w;
            acc[q * 4 + 1] += m.y * w;
            acc[q * 4 + 2] += m.z * w;
            acc[q * 4 + 3] += m.w * w;
        }
    }
    const float4* f0 = (const float4*)(fin + (size_t)n * 24);
    float4* fo = (float4*)(fout + (size_t)n * 24);
#pragma unroll
    for (int q = 0; q < 6; q++) {
        float4 f = f0[q];
        fo[q] = make_float4(0.5f * f.x + acc[q * 4 + 0],
                            0.5f * f.y + acc[q * 4 + 1],
                            0.5f * f.z + acc[q * 4 + 2],
                            0.5f * f.w + acc[q * 4 + 3]);
    }
}

// last step: gather + write directly to out in [b][n][3] layout
__global__ void k_gather_out(const float* __restrict__ fin,
                             float* __restrict__ out) {
    int n = blockIdx.x * 256 + threadIdx.x;
    if (n >= ND) return;
    int beg = g_rowptr[n];
    int end = g_rowptr[n + 1];
    float acc[24];
#pragma unroll
    for (int t = 0; t < 24; t++) acc[t] = 0.f;
    for (int i = beg; i < end; i++) {
        int2 r = g_recs[i];
        float w = __int_as_float(r.y);
        const float4* fs = (const float4*)(fin + r.x);
#pragma unroll
        for (int q = 0; q < 6; q++) {
            float4 m = fs[q];
            acc[q * 4 + 0] += m.x * w;
            acc[q * 4 + 1] += m.y * w;
            acc[q * 4 + 2] += m.z * w;
            acc[q * 4 + 3] += m.w * w;
        }
    }
    const float* f0 = fin + (size_t)n * 24;
#pragma unroll
    for (int b = 0; b < NB; b++) {
        float* op = out + (size_t)b * (ND * 3) + (size_t)n * 3;
#pragma unroll
        for (int a = 0; a < 3; a++)
            op[a] = 0.5f * f0[b * 3 + a] + acc[b * 3 + a];
    }
}

__global__ void k_reg(float* __restrict__ out, int do_write) {
    if (do_write) out[(size_t)NB * ND * 3] = 1e-4f * sqrtf(g_regsum);
}

// ---------------------------------------------------------------------------
extern "C" void kernel_launch(void* const* d_in, const int* in_sizes, int n_in,
                              void* d_out, int out_size) {
    const float* latent = (const float*)d_in[0];
    const float* W0 = (const float*)d_in[1];
    const float* b0 = (const float*)d_in[2];
    const float* W1 = (const float*)d_in[3];
    const float* b1 = (const float*)d_in[4];
    const float* W2 = (const float*)d_in[5];
    const float* b2 = (const float*)d_in[6];
    const float* W3 = (const float*)d_in[7];
    const float* b3 = (const float*)d_in[8];
    const float* Wx = (const float*)d_in[9];
    const float* bx = (const float*)d_in[10];
    const float* Wy = (const float*)d_in[11];
    const float* by = (const float*)d_in[12];
    const float* Wz = (const float*)d_in[13];
    const float* bz = (const float*)d_in[14];
    const float* Z  = (const float*)d_in[15];
    const float* ew = (const float*)d_in[16];
    const int*   ei = (const int*)d_in[17];   // int32 OR int64 (auto-detected)
    float* out = (float*)d_out;

    void *p_f, *p_fb, *p_reg, *p_count, *p_wdeg, *p_h0, *p_h1;
    cudaGetSymbolAddress(&p_f, g_f);
    cudaGetSymbolAddress(&p_fb, g_fb);
    cudaGetSymbolAddress(&p_reg, g_regsum);
    cudaGetSymbolAddress(&p_count, g_count);
    cudaGetSymbolAddress(&p_wdeg, g_wdeg);
    cudaGetSymbolAddress(&p_h0, g_hT0);
    cudaGetSymbolAddress(&p_h1, g_hT1);

    static cudaStream_t s2 = nullptr;
    static cudaEvent_t evFork = nullptr, evJoin = nullptr;
    if (!s2) {
        cudaStreamCreateWithFlags(&s2, cudaStreamNonBlocking);
        cudaEventCreateWithFlags(&evFork, cudaEventDisableTiming);
        cudaEventCreateWithFlags(&evJoin, cudaEventDisableTiming);
        cudaFuncSetAttribute(k_gemm, cudaFuncAttributeMaxDynamicSharedMemorySize,
                             KD * 24 * 8);
    }

    // ---- fork: CSR build on s2, MLP+GEMM on capture stream -----------------
    cudaEventRecord(evFork, 0);
    cudaStreamWaitEvent(s2, evFork, 0);

    cudaMemsetAsync(p_count, 0, (size_t)ND * sizeof(int), s2);
    cudaMemsetAsync(p_wdeg, 0, (size_t)ND * sizeof(float), s2);
    k_detect<<<1, 256, 0, s2>>>(ei);
    k_hist<<<(ED + 255) / 256, 256, 0, s2>>>(ei, ew);
    k_scan<<<1, 1024, 0, s2>>>();
    k_fill<<<(ED + 255) / 256, 256, 0, s2>>>(ei, ew);
    cudaEventRecord(evJoin, s2);

    cudaMemsetAsync(p_reg, 0, sizeof(float));

    // MLP decode (split-K, no atomics)
    k_mlp0_splitK<<<dim3(8, NCH_0), 128>>>(latent, W0);
    k_epi<NCH_0, false><<<8, 128>>>(nullptr, (float*)p_h0, b0);
    k_layer_splitK<<<dim3(8, NCH_L), 128>>>((float*)p_h0, W1);
    k_epi<NCH_L, true><<<8, 128>>>((float*)p_h0, (float*)p_h1, b1);
    k_layer_splitK<<<dim3(8, NCH_L), 128>>>((float*)p_h1, W2);
    k_epi<NCH_L, true><<<8, 128>>>((float*)p_h1, (float*)p_h0, b2);
    k_layer_splitK<<<dim3(8, NCH_L), 128>>>((float*)p_h0, W3);
    k_epi<NCH_L, true><<<8, 128>>>((float*)p_h0, (float*)p_h1, b3);
    k_coeff_splitK<<<dim3(3, NCH_C), 320>>>((float*)p_h1, Wx, Wy, Wz);
    k_coeff_epi<<<1, 320>>>(bx, by, bz);

    // dense projection onto basis Z (packed f32x2 FMA)
    k_gemm<<<(ND + 255) / 256, 64, KD * 24 * 8>>>(Z);

    // ---- join: diffusion needs both GEMM (this stream) and CSR (s2) --------
    cudaStreamWaitEvent(0, evJoin, 0);

    k_gather<<<(ND + 255) / 256, 256>>>((float*)p_f,  (float*)p_fb);
    k_gather<<<(ND + 255) / 256, 256>>>((float*)p_fb, (float*)p_f);
    k_gather_out<<<(ND + 255) / 256, 256>>>((float*)p_f, out);

    k_reg<<<1, 1>>>(out, (out_size > NB * ND * 3) ? 1 : 0);
}

// round 14
// speedup vs baseline: 2.8554x; 1.2949x over previous
#include <cuda_runtime.h>
#include <cstdint>
#include <math.h>

#define NB    8
#define LATD  128
#define HD    1024
#define KD    294
#define ND    100000
#define ED    1600000
#define NCH_L 16        // split-K chunks for residual layers (chunk = 64 rows)
#define NCH_0 4         // chunks for layer 0 (chunk = 32 rows)
#define NCH_C 16        // chunks for coeff heads (chunk = 64 rows)
#define NSB   98        // scan blocks: ceil(ND/1024)

// ---------------- scratch (device globals; no allocation allowed) ----------
__device__ __align__(16) float g_hT0[HD * NB];            // [j][b]
__device__ __align__(16) float g_hT1[HD * NB];
__device__ __align__(16) float g_part[NCH_L * HD * NB];   // layer partials [ch][j][b]
__device__ __align__(16) float g_cpart[3 * NCH_C * KD * NB];
__device__ __align__(16) float2 g_cbuf2[KD * 24];         // duplicated (c,c), x64
__device__ __align__(16) float g_f[(size_t)ND * 24];      // [n][b*3+axis]
__device__ __align__(16) float g_fb[(size_t)ND * 24];
__device__ float g_regsum;
__device__ int   g_is64;
// CSR
__device__ int   g_count[ND];
__device__ float g_wdeg[ND];
__device__ int   g_rowptr[ND + 1];
__device__ int   g_cursor[ND];
__device__ int   g_bsum[NSB];
__device__ int   g_boff[NSB];
__device__ __align__(8) int2 g_recs[ED];   // {src*24, bitcast(w')} grouped by dst

// ---------------- edge_index dtype detection --------------------------------
__global__ void k_detect(const int* __restrict__ ei32) {
    __shared__ int any_nonzero;
    int t = threadIdx.x;
    if (t == 0) any_nonzero = 0;
    __syncthreads();
    int v = ei32[2 * (t * 64) + 1];
    if (v != 0) atomicOr(&any_nonzero, 1);
    __syncthreads();
    if (t == 0) g_is64 = (any_nonzero == 0) ? 1 : 0;
}

__device__ __forceinline__ int load_ei(const int* __restrict__ ei32, size_t pos) {
    return g_is64 ? ei32[2 * pos] : ei32[pos];
}

// ---------------- layer 0 split-K: chunk = 32 latent rows -------------------
__global__ void k_mlp0_splitK(const float* __restrict__ latent,
                              const float* __restrict__ W0) {
    __shared__ float slat[32 * NB];                   // [ii][b]
    int tid = threadIdx.x;
    int ch = blockIdx.y;
    int i0 = ch * 32;
    for (int idx = tid; idx < 32 * NB; idx += 128) {
        int ii = idx >> 3, b = idx & 7;
        slat[ii * NB + b] = latent[b * LATD + i0 + ii];
    }
    __syncthreads();
    int j = blockIdx.x * 128 + tid;
    float acc[NB];
#pragma unroll
    for (int b = 0; b < NB; b++) acc[b] = 0.f;
    const float* Wp = W0 + (size_t)i0 * HD + j;
#pragma unroll 8
    for (int ii = 0; ii < 32; ii++) {
        float w = Wp[(size_t)ii * HD];
        const float4* h4 = (const float4*)&slat[ii * NB];
        float4 a = h4[0], c = h4[1];
        acc[0] += a.x * w; acc[1] += a.y * w; acc[2] += a.z * w; acc[3] += a.w * w;
        acc[4] += c.x * w; acc[5] += c.y * w; acc[6] += c.z * w; acc[7] += c.w * w;
    }
    float4* dst = (float4*)&g_part[((size_t)ch * HD + j) * NB];
    dst[0] = make_float4(acc[0], acc[1], acc[2], acc[3]);
    dst[1] = make_float4(acc[4], acc[5], acc[6], acc[7]);
}

// -------- residual layer split-K: chunk = 64 rows ---------------------------
__global__ void k_layer_splitK(const float* __restrict__ hT,
                               const float* __restrict__ W) {
    __shared__ __align__(16) float sh[64 * NB];       // [ii][b]
    int tid = threadIdx.x;
    int ch = blockIdx.y;
    int i0 = ch * 64;
    const float4* src = (const float4*)(hT + (size_t)i0 * NB);
    ((float4*)sh)[tid] = src[tid];
    __syncthreads();
    int j = blockIdx.x * 128 + tid;
    float acc[NB];
#pragma unroll
    for (int b = 0; b < NB; b++) acc[b] = 0.f;
    const float* Wp = W + (size_t)i0 * HD + j;
#pragma unroll 16
    for (int ii = 0; ii < 64; ii++) {
        float w = Wp[(size_t)ii * HD];
        const float4* h4 = (const float4*)&sh[ii * NB];
        float4 a = h4[0], c = h4[1];
        acc[0] += a.x * w; acc[1] += a.y * w; acc[2] += a.z * w; acc[3] += a.w * w;
        acc[4] += c.x * w; acc[5] += c.y * w; acc[6] += c.z * w; acc[7] += c.w * w;
    }
    float4* dst = (float4*)&g_part[((size_t)ch * HD + j) * NB];
    dst[0] = make_float4(acc[0], acc[1], acc[2], acc[3]);
    dst[1] = make_float4(acc[4], acc[5], acc[6], acc[7]);
}

// epilogue: reduce chunks (+bias, +optional residual), relu
template <int NCHUNKS, bool RES>
__global__ void k_epi(const float* __restrict__ hT_in,
                      float* __restrict__ hT_out,
                      const float* __restrict__ bias) {
    int j = blockIdx.x * 128 + threadIdx.x;
    float bb = bias[j];
    float acc[NB];
#pragma unroll
    for (int b = 0; b < NB; b++) acc[b] = RES ? (hT_in[j * NB + b] + bb) : bb;
#pragma unroll
    for (int c = 0; c < NCHUNKS; c++) {
        const float4* p = (const float4*)&g_part[((size_t)c * HD + j) * NB];
        float4 a = p[0], d = p[1];
        acc[0] += a.x; acc[1] += a.y; acc[2] += a.z; acc[3] += a.w;
        acc[4] += d.x; acc[5] += d.y; acc[6] += d.z; acc[7] += d.w;
    }
#pragma unroll
    for (int b = 0; b < NB; b++) hT_out[j * NB + b] = fmaxf(acc[b], 0.f);
}

// -------- coefficient heads split-K: chunk = 64 rows ------------------------
__global__ void k_coeff_splitK(const float* __restrict__ hT,
                               const float* __restrict__ Wx,
                               const float* __restrict__ Wy,
                               const float* __restrict__ Wz) {
    __shared__ __align__(16) float sh[64 * NB];
    int tid = threadIdx.x;
    int ch = blockIdx.y;
    int i0 = ch * 64;
    const float4* src = (const float4*)(hT + (size_t)i0 * NB);
    if (tid < 128) ((float4*)sh)[tid] = src[tid];
    __syncthreads();
    int k = tid;
    if (k >= KD) return;
    int axis = blockIdx.x;
    const float* W = (axis == 0) ? Wx : ((axis == 1) ? Wy : Wz);
    const float* Wp = W + (size_t)i0 * KD + k;
    float acc[NB];
#pragma unroll
    for (int b = 0; b < NB; b++) acc[b] = 0.f;
#pragma unroll 8
    for (int ii = 0; ii < 64; ii++) {
        float w = Wp[(size_t)ii * KD];
        const float4* h4 = (const float4*)&sh[ii * NB];
        float4 a = h4[0], c = h4[1];
        acc[0] += a.x * w; acc[1] += a.y * w; acc[2] += a.z * w; acc[3] += a.w * w;
        acc[4] += c.x * w; acc[5] += c.y * w; acc[6] += c.z * w; acc[7] += c.w * w;
    }
    float4* dst = (float4*)&g_cpart[(((size_t)axis * NCH_C + ch) * KD + k) * NB];
    dst[0] = make_float4(acc[0], acc[1], acc[2], acc[3]);
    dst[1] = make_float4(acc[4], acc[5], acc[6], acc[7]);
}

// epi: reduce chunks, write duplicated x64 pairs to g_cbuf2, accumulate reg
__global__ void k_coeff_epi(const float* __restrict__ bx,
                            const float* __restrict__ by,
                            const float* __restrict__ bz) {
    int k = threadIdx.x;
    float ss = 0.f;
    if (k < KD) {
#pragma unroll
        for (int axis = 0; axis < 3; axis++) {
            const float* bias = (axis == 0) ? bx : ((axis == 1) ? by : bz);
            float bb = bias[k];
            float acc[NB];
#pragma unroll
            for (int b = 0; b < NB; b++) acc[b] = bb;
#pragma unroll
            for (int c = 0; c < NCH_C; c++) {
                const float4* p = (const float4*)&g_cpart[(((size_t)axis * NCH_C + c) * KD + k) * NB];
                float4 a = p[0], d = p[1];
                acc[0] += a.x; acc[1] += a.y; acc[2] += a.z; acc[3] += a.w;
                acc[4] += d.x; acc[5] += d.y; acc[6] += d.z; acc[7] += d.w;
            }
#pragma unroll
            for (int b = 0; b < NB; b++) {
                float v = acc[b];
                ss += v * v;
                float sv = 64.f * v;
                g_cbuf2[k * 24 + b * 3 + axis] = make_float2(sv, sv);
            }
        }
    }
#pragma unroll
    for (int off = 16; off > 0; off >>= 1)
        ss += __shfl_down_sync(0xFFFFFFFFu, ss, off);
    if ((threadIdx.x & 31) == 0) atomicAdd(&g_regsum, ss);
}

// -------- big GEMM: packed f32x2 FMA + 4-deep register prefetch -------------
__device__ __forceinline__ void gstep(unsigned long long* acc2,
                                      const unsigned long long* crow,
                                      unsigned long long zp0,
                                      unsigned long long zp1) {
    const ulonglong2* cr = (const ulonglong2*)crow;
#pragma unroll
    for (int q = 0; q < 12; q++) {
        ulonglong2 c = cr[q];
        int j0 = q * 2;
        asm("fma.rn.f32x2 %0, %1, %2, %0;" : "+l"(acc2[j0 * 2 + 0]) : "l"(c.x), "l"(zp0));
        asm("fma.rn.f32x2 %0, %1, %2, %0;" : "+l"(acc2[j0 * 2 + 1]) : "l"(c.x), "l"(zp1));
        asm("fma.rn.f32x2 %0, %1, %2, %0;" : "+l"(acc2[j0 * 2 + 2]) : "l"(c.y), "l"(zp0));
        asm("fma.rn.f32x2 %0, %1, %2, %0;" : "+l"(acc2[j0 * 2 + 3]) : "l"(c.y), "l"(zp1));
    }
}

__global__ __launch_bounds__(64) void k_gemm(const float* __restrict__ Z) {
    extern __shared__ __align__(16) unsigned long long cs[];  // KD*24 u64 pairs
    int tid = threadIdx.x;
    const ulonglong2* src = (const ulonglong2*)g_cbuf2;
    ulonglong2* d2 = (ulonglong2*)cs;
    for (int t = tid; t < KD * 12; t += 64) d2[t] = src[t];
    __syncthreads();
    int n = blockIdx.x * 256 + tid * 4;
    if (n >= ND) return;
    unsigned long long acc2[48];
#pragma unroll
    for (int t = 0; t < 48; t++) acc2[t] = 0ULL;
    const ulonglong2* Zp = (const ulonglong2*)(Z + n);
    const size_t str = ND / 4;
    ulonglong2 z0 = Zp[0], z1 = Zp[str], z2 = Zp[2 * str], z3 = Zp[3 * str];
#pragma unroll 1
    for (int k0 = 0; k0 < 285; k0 += 4) {            // computes k = 0..287
        ulonglong2 w0 = Zp[(size_t)(k0 + 4) * str];
        ulonglong2 w1 = Zp[(size_t)(k0 + 5) * str];
        ulonglong2 w2 = Zp[(size_t)(k0 + 6) * str];
        ulonglong2 w3 = Zp[(size_t)(k0 + 7) * str];
        gstep(acc2, cs + (size_t)(k0 + 0) * 24, z0.x, z0.y);
        gstep(acc2, cs + (size_t)(k0 + 1) * 24, z1.x, z1.y);
        gstep(acc2, cs + (size_t)(k0 + 2) * 24, z2.x, z2.y);
        gstep(acc2, cs + (size_t)(k0 + 3) * 24, z3.x, z3.y);
        z0 = w0; z1 = w1; z2 = w2; z3 = w3;
    }
    gstep(acc2, cs + 288 * 24, z0.x, z0.y);          // k = 288..291
    gstep(acc2, cs + 289 * 24, z1.x, z1.y);
    gstep(acc2, cs + 290 * 24, z2.x, z2.y);
    gstep(acc2, cs + 291 * 24, z3.x, z3.y);
    z0 = Zp[292 * str]; z1 = Zp[293 * str];          // k = 292, 293
    gstep(acc2, cs + 292 * 24, z0.x, z0.y);
    gstep(acc2, cs + 293 * 24, z1.x, z1.y);

    float vals[96];
#pragma unroll
    for (int j = 0; j < 24; j++) {
#pragma unroll
        for (int p = 0; p < 2; p++) {
            float lo, hi;
            asm("mov.b64 {%0,%1}, %2;" : "=f"(lo), "=f"(hi) : "l"(acc2[j * 2 + p]));
            vals[j * 4 + 2 * p]     = lo;
            vals[j * 4 + 2 * p + 1] = hi;
        }
    }
#pragma unroll
    for (int comp = 0; comp < 4; comp++) {
        float4* out = (float4*)(g_f + (size_t)(n + comp) * 24);
#pragma unroll
        for (int q = 0; q < 6; q++)
            out[q] = make_float4(vals[(q * 4 + 0) * 4 + comp],
                                 vals[(q * 4 + 1) * 4 + comp],
                                 vals[(q * 4 + 2) * 4 + comp],
                                 vals[(q * 4 + 3) * 4 + comp]);
    }
}

// ---------------- CSR build -------------------------------------------------
__global__ void k_hist(const int* __restrict__ ei32,
                       const float* __restrict__ ew) {
    int e = blockIdx.x * 256 + threadIdx.x;
    if (e >= ED) return;
    int d = load_ei(ei32, (size_t)ED + e);
    if ((unsigned)d >= ND) return;
    atomicAdd(&g_count[d], 1);
    atomicAdd(&g_wdeg[d], ew[e]);
}

// parallel scan: block reduce -> serial 98-scan -> block-local prefix
__global__ void k_scan1() {                          // grid NSB, block 1024
    __shared__ int sred[32];
    int b = blockIdx.x, t = threadIdx.x;
    int idx = b * 1024 + t;
    int v = (idx < ND) ? g_count[idx] : 0;
    int s = v;
#pragma unroll
    for (int off = 16; off > 0; off >>= 1)
        s += __shfl_down_sync(0xFFFFFFFFu, s, off);
    if ((t & 31) == 0) sred[t >> 5] = s;
    __syncthreads();
    if (t < 32) {
        int x = sred[t];
#pragma unroll
        for (int off = 16; off > 0; off >>= 1)
            x += __shfl_down_sync(0xFFFFFFFFu, x, off);
        if (t == 0) g_bsum[b] = x;
    }
}

__global__ void k_scan2() {                          // 1 thread
    int run = 0;
    for (int b = 0; b < NSB; b++) { g_boff[b] = run; run += g_bsum[b]; }
    g_rowptr[ND] = run;
}

__global__ void k_scan3() {                          // grid NSB, block 1024
    __shared__ int sp[1024];
    int b = blockIdx.x, t = threadIdx.x;
    int idx = b * 1024 + t;
    int v = (idx < ND) ? g_count[idx] : 0;
    sp[t] = v;
    __syncthreads();
    for (int off = 1; off < 1024; off <<= 1) {
        int x = (t >= off) ? sp[t - off] : 0;
        __syncthreads();
        sp[t] += x;
        __syncthreads();
    }
    if (idx < ND) {
        int excl = g_boff[b] + sp[t] - v;
        g_rowptr[idx] = excl;
        g_cursor[idx] = excl;
    }
}

__global__ void k_fill(const int* __restrict__ ei32,
                       const float* __restrict__ ew) {
    int e = blockIdx.x * 256 + threadIdx.x;
    if (e >= ED) return;
    int s = load_ei(ei32, (size_t)e);
    int d = load_ei(ei32, (size_t)ED + e);
    if ((unsigned)s >= ND || (unsigned)d >= ND) return;
    float wp = 0.5f * ew[e] / fmaxf(g_wdeg[d], 1e-6f);
    int slot = atomicAdd(&g_cursor[d], 1);
    g_recs[slot] = make_int2(s * 24, __float_as_int(wp));
}

// ---------------- diffusion: 2 threads per node, fused combine --------------
__global__ __launch_bounds__(256) void k_gather(const float* __restrict__ fin,
                                                float* __restrict__ fout) {
    int g = blockIdx.x * 256 + threadIdx.x;
    if (g >= 2 * ND) return;
    int n = g >> 1;
    int h = (g & 1) * 12;
    int beg = g_rowptr[n], end = g_rowptr[n + 1];
    float acc[12];
#pragma unroll
    for (int t = 0; t < 12; t++) acc[t] = 0.f;
    int i = beg;
    for (; i + 2 <= end; i += 2) {
        int2 r0 = g_recs[i], r1 = g_recs[i + 1];
        float w0 = __int_as_float(r0.y), w1 = __int_as_float(r1.y);
        const float4* a0 = (const float4*)(fin + r0.x + h);
        const float4* a1 = (const float4*)(fin + r1.x + h);
        float4 m0 = a0[0], m1 = a0[1], m2 = a0[2];
        float4 p0 = a1[0], p1 = a1[1], p2 = a1[2];
        acc[0] += m0.x * w0; acc[1] += m0.y * w0; acc[2]  += m0.z * w0; acc[3]  += m0.w * w0;
        acc[4] += m1.x * w0; acc[5] += m1.y * w0; acc[6]  += m1.z * w0; acc[7]  += m1.w * w0;
        acc[8] += m2.x * w0; acc[9] += m2.y * w0; acc[10] += m2.z * w0; acc[11] += m2.w * w0;
        acc[0] += p0.x * w1; acc[1] += p0.y * w1; acc[2]  += p0.z * w1; acc[3]  += p0.w * w1;
        acc[4] += p1.x * w1; acc[5] += p1.y * w1; acc[6]  += p1.z * w1; acc[7]  += p1.w * w1;
        acc[8] += p2.x * w1; acc[9] += p2.y * w1; acc[10] += p2.z * w1; acc[11] += p2.w * w1;
    }
    if (i < end) {
        int2 r0 = g_recs[i];
        float w0 = __int_as_float(r0.y);
        const float4* a0 = (const float4*)(fin + r0.x + h);
        float4 m0 = a0[0], m1 = a0[1], m2 = a0[2];
        acc[0] += m0.x * w0; acc[1] += m0.y * w0; acc[2]  += m0.z * w0; acc[3]  += m0.w * w0;
        acc[4] += m1.x * w0; acc[5] += m1.y * w0; acc[6]  += m1.z * w0; acc[7]  += m1.w * w0;
        acc[8] += m2.x * w0; acc[9] += m2.y * w0; acc[10] += m2.z * w0; acc[11] += m2.w * w0;
    }
    const float4* f0 = (const float4*)(fin + (size_t)n * 24 + h);
    float4* fo = (float4*)(fout + (size_t)n * 24 + h);
#pragma unroll
    for (int q = 0; q < 3; q++) {
        float4 f = f0[q];
        fo[q] = make_float4(0.5f * f.x + acc[q * 4 + 0],
                            0.5f * f.y + acc[q * 4 + 1],
                            0.5f * f.z + acc[q * 4 + 2],
                            0.5f * f.w + acc[q * 4 + 3]);
    }
}

// last step: gather + write directly to out in [b][n][3] layout
__global__ __launch_bounds__(256) void k_gather_out(const float* __restrict__ fin,
                                                    float* __restrict__ out) {
    int g = blockIdx.x * 256 + threadIdx.x;
    if (g >= 2 * ND) return;
    int n = g >> 1;
    int h = (g & 1) * 12;
    int beg = g_rowptr[n], end = g_rowptr[n + 1];
    float acc[12];
#pragma unroll
    for (int t = 0; t < 12; t++) acc[t] = 0.f;
    int i = beg;
    for (; i + 2 <= end; i += 2) {
        int2 r0 = g_recs[i], r1 = g_recs[i + 1];
        float w0 = __int_as_float(r0.y), w1 = __int_as_float(r1.y);
        const float4* a0 = (const float4*)(fin + r0.x + h);
        const float4* a1 = (const float4*)(fin + r1.x + h);
        float4 m0 = a0[0], m1 = a0[1], m2 = a0[2];
        float4 p0 = a1[0], p1 = a1[1], p2 = a1[2];
        acc[0] += m0.x * w0; acc[1] += m0.y * w0; acc[2]  += m0.z * w0; acc[3]  += m0.w * w0;
        acc[4] += m1.x * w0; acc[5] += m1.y * w0; acc[6]  += m1.z * w0; acc[7]  += m1.w * w0;
        acc[8] += m2.x * w0; acc[9] += m2.y * w0; acc[10] += m2.z * w0; acc[11] += m2.w * w0;
        acc[0] += p0.x * w1; acc[1] += p0.y * w1; acc[2]  += p0.z * w1; acc[3]  += p0.w * w1;
        acc[4] += p1.x * w1; acc[5] += p1.y * w1; acc[6]  += p1.z * w1; acc[7]  += p1.w * w1;
        acc[8] += p2.x * w1; acc[9] += p2.y * w1; acc[10] += p2.z * w1; acc[11] += p2.w * w1;
    }
    if (i < end) {
        int2 r0 = g_recs[i];
        float w0 = __int_as_float(r0.y);
        const float4* a0 = (const float4*)(fin + r0.x + h);
        float4 m0 = a0[0], m1 = a0[1], m2 = a0[2];
        acc[0] += m0.x * w0; acc[1] += m0.y * w0; acc[2]  += m0.z * w0; acc[3]  += m0.w * w0;
        acc[4] += m1.x * w0; acc[5] += m1.y * w0; acc[6]  += m1.z * w0; acc[7]  += m1.w * w0;
        acc[8] += m2.x * w0; acc[9] += m2.y * w0; acc[10] += m2.z * w0; acc[11] += m2.w * w0;
    }
    const float* f0 = fin + (size_t)n * 24 + h;
    int bbase = (h == 0) ? 0 : 4;
#pragma unroll
    for (int bb = 0; bb < 4; bb++) {
        float* op = out + (size_t)(bbase + bb) * (ND * 3) + (size_t)n * 3;
#pragma unroll
        for (int a = 0; a < 3; a++)
            op[a] = 0.5f * f0[bb * 3 + a] + acc[bb * 3 + a];
    }
}

__global__ void k_reg(float* __restrict__ out, int do_write) {
    if (do_write) out[(size_t)NB * ND * 3] = 1e-4f * sqrtf(g_regsum);
}

// ---------------------------------------------------------------------------
extern "C" void kernel_launch(void* const* d_in, const int* in_sizes, int n_in,
                              void* d_out, int out_size) {
    const float* latent = (const float*)d_in[0];
    const float* W0 = (const float*)d_in[1];
    const float* b0 = (const float*)d_in[2];
    const float* W1 = (const float*)d_in[3];
    const float* b1 = (const float*)d_in[4];
    const float* W2 = (const float*)d_in[5];
    const float* b2 = (const float*)d_in[6];
    const float* W3 = (const float*)d_in[7];
    const float* b3 = (const float*)d_in[8];
    const float* Wx = (const float*)d_in[9];
    const float* bx = (const float*)d_in[10];
    const float* Wy = (const float*)d_in[11];
    const float* by = (const float*)d_in[12];
    const float* Wz = (const float*)d_in[13];
    const float* bz = (const float*)d_in[14];
    const float* Z  = (const float*)d_in[15];
    const float* ew = (const float*)d_in[16];
    const int*   ei = (const int*)d_in[17];   // int32 OR int64 (auto-detected)
    float* out = (float*)d_out;

    void *p_f, *p_fb, *p_reg, *p_count, *p_wdeg, *p_h0, *p_h1;
    cudaGetSymbolAddress(&p_f, g_f);
    cudaGetSymbolAddress(&p_fb, g_fb);
    cudaGetSymbolAddress(&p_reg, g_regsum);
    cudaGetSymbolAddress(&p_count, g_count);
    cudaGetSymbolAddress(&p_wdeg, g_wdeg);
    cudaGetSymbolAddress(&p_h0, g_hT0);
    cudaGetSymbolAddress(&p_h1, g_hT1);

    static cudaStream_t s2 = nullptr;
    static cudaEvent_t evFork = nullptr, evJoin = nullptr;
    if (!s2) {
        cudaStreamCreateWithFlags(&s2, cudaStreamNonBlocking);
        cudaEventCreateWithFlags(&evFork, cudaEventDisableTiming);
        cudaEventCreateWithFlags(&evJoin, cudaEventDisableTiming);
        cudaFuncSetAttribute(k_gemm, cudaFuncAttributeMaxDynamicSharedMemorySize,
                             KD * 24 * 8);
    }

    // ---- fork: CSR build on s2, MLP+GEMM on capture stream -----------------
    cudaEventRecord(evFork, 0);
    cudaStreamWaitEvent(s2, evFork, 0);

    cudaMemsetAsync(p_count, 0, (size_t)ND * sizeof(int), s2);
    cudaMemsetAsync(p_wdeg, 0, (size_t)ND * sizeof(float), s2);
    k_detect<<<1, 256, 0, s2>>>(ei);
    k_hist<<<(ED + 255) / 256, 256, 0, s2>>>(ei, ew);
    k_scan1<<<NSB, 1024, 0, s2>>>();
    k_scan2<<<1, 1, 0, s2>>>();
    k_scan3<<<NSB, 1024, 0, s2>>>();
    k_fill<<<(ED + 255) / 256, 256, 0, s2>>>(ei, ew);
    cudaEventRecord(evJoin, s2);

    cudaMemsetAsync(p_reg, 0, sizeof(float));

    // MLP decode (split-K, no atomics)
    k_mlp0_splitK<<<dim3(8, NCH_0), 128>>>(latent, W0);
    k_epi<NCH_0, false><<<8, 128>>>(nullptr, (float*)p_h0, b0);
    k_layer_splitK<<<dim3(8, NCH_L), 128>>>((float*)p_h0, W1);
    k_epi<NCH_L, true><<<8, 128>>>((float*)p_h0, (float*)p_h1, b1);
    k_layer_splitK<<<dim3(8, NCH_L), 128>>>((float*)p_h1, W2);
    k_epi<NCH_L, true><<<8, 128>>>((float*)p_h1, (float*)p_h0, b2);
    k_layer_splitK<<<dim3(8, NCH_L), 128>>>((float*)p_h0, W3);
    k_epi<NCH_L, true><<<8, 128>>>((float*)p_h0, (float*)p_h1, b3);
    k_coeff_splitK<<<dim3(3, NCH_C), 320>>>((float*)p_h1, Wx, Wy, Wz);
    k_coeff_epi<<<1, 320>>>(bx, by, bz);

    // reg scalar is ready now; write it while GEMM runs
    k_reg<<<1, 1>>>(out, (out_size > NB * ND * 3) ? 1 : 0);

    // dense projection onto basis Z (packed f32x2 FMA, pipelined)
    k_gemm<<<(ND + 255) / 256, 64, KD * 24 * 8>>>(Z);

    // ---- join: diffusion needs both GEMM (this stream) and CSR (s2) --------
    cudaStreamWaitEvent(0, evJoin, 0);

    k_gather<<<(2 * ND + 255) / 256, 256>>>((float*)p_f,  (float*)p_fb);
    k_gather<<<(2 * ND + 255) / 256, 256>>>((float*)p_fb, (float*)p_f);
    k_gather_out<<<(2 * ND + 255) / 256, 256>>>((float*)p_f, out);
}

// round 17
// speedup vs baseline: 2.8927x; 1.0131x over previous
#include <cuda_runtime.h>
#include <cstdint>
#include <math.h>

#define NB    8
#define LATD  128
#define HD    1024
#define KD    294
#define ND    100000
#define ED    1600000
#define NCH_L 16        // split-K chunks for residual layers (chunk = 64 rows)
#define NCH_0 4         // chunks for layer 0 (chunk = 32 rows)
#define NCH_C 16        // chunks for coeff heads (chunk = 64 rows)
#define NSB   98        // scan blocks: ceil(ND/1024)

// ---------------- scratch (device globals; no allocation allowed) ----------
__device__ __align__(16) float g_hA[HD * NB];             // [j][b]
__device__ __align__(16) float g_hB[HD * NB];
__device__ __align__(16) float g_partA[NCH_L * HD * NB];  // [ch][j][b]
__device__ __align__(16) float g_partB[NCH_L * HD * NB];
__device__ __align__(16) float g_cpart[3 * NCH_C * KD * NB];
__device__ __align__(16) float2 g_cbuf2[KD * 24];         // duplicated (c,c), x64
__device__ __align__(16) float g_f[(size_t)ND * 24];      // [n][b*3+axis]
__device__ __align__(16) float g_fb[(size_t)ND * 24];
__device__ int   g_is64;
// CSR (count and wdeg unified for a single memset)
__device__ __align__(16) int g_cw[2 * ND];                // [0,ND)=count, [ND,2ND)=wdeg bits
__device__ int   g_rowptr[ND + 1];
__device__ int   g_cursor[ND];
__device__ int   g_bsum[NSB];
__device__ int   g_boff[NSB];
__device__ __align__(8) int2 g_recs[ED];   // {src*24, bitcast(w')} grouped by dst

__device__ __forceinline__ int load_ei(const int* __restrict__ ei32, size_t pos, int is64) {
    return is64 ? ei32[2 * pos] : ei32[pos];
}

// ---------------- layer 0 split-K: chunk = 32 latent rows -------------------
__global__ void k_mlp0_splitK(const float* __restrict__ latent,
                              const float* __restrict__ W0) {
    __shared__ float slat[32 * NB];                   // [ii][b]
    int tid = threadIdx.x;
    int ch = blockIdx.y;
    int i0 = ch * 32;
    for (int idx = tid; idx < 32 * NB; idx += 128) {
        int ii = idx >> 3, b = idx & 7;
        slat[ii * NB + b] = latent[b * LATD + i0 + ii];
    }
    __syncthreads();
    int j = blockIdx.x * 128 + tid;
    float acc[NB];
#pragma unroll
    for (int b = 0; b < NB; b++) acc[b] = 0.f;
    const float* Wp = W0 + (size_t)i0 * HD + j;
#pragma unroll 8
    for (int ii = 0; ii < 32; ii++) {
        float w = Wp[(size_t)ii * HD];
        const float4* h4 = (const float4*)&slat[ii * NB];
        float4 a = h4[0], c = h4[1];
        acc[0] += a.x * w; acc[1] += a.y * w; acc[2] += a.z * w; acc[3] += a.w * w;
        acc[4] += c.x * w; acc[5] += c.y * w; acc[6] += c.z * w; acc[7] += c.w * w;
    }
    float4* dst = (float4*)&g_partA[((size_t)ch * HD + j) * NB];
    dst[0] = make_float4(acc[0], acc[1], acc[2], acc[3]);
    dst[1] = make_float4(acc[4], acc[5], acc[6], acc[7]);
}

// -------- fused: finalize previous layer's h (64 rows) + split-K MM ---------
template <int NCH_IN, bool RES, bool WRITEH>
__global__ void k_layerF(const float* __restrict__ hResid,
                         const float* __restrict__ partIn,
                         float* __restrict__ partOut,
                         float* __restrict__ hOut,
                         const float* __restrict__ bias,
                         const float* __restrict__ W) {
    __shared__ __align__(16) float sh[64 * NB];       // finalized h rows [ii][b]
    int tid = threadIdx.x;
    int ch = blockIdx.y;
    int i0 = ch * 64;
    {   // step A: finalize h for rows i0..i0+63 (2 threads per row)
        int jj = i0 + (tid >> 1);
        int half = tid & 1;
        float bb = bias[jj];
        float4 a = make_float4(bb, bb, bb, bb);
        if (RES) {
            float4 r = ((const float4*)(hResid + (size_t)jj * NB))[half];
            a.x += r.x; a.y += r.y; a.z += r.z; a.w += r.w;
        }
#pragma unroll
        for (int c = 0; c < NCH_IN; c++) {
            float4 p = ((const float4*)(partIn + ((size_t)c * HD + jj) * NB))[half];
            a.x += p.x; a.y += p.y; a.z += p.z; a.w += p.w;
        }
        a.x = fmaxf(a.x, 0.f); a.y = fmaxf(a.y, 0.f);
        a.z = fmaxf(a.z, 0.f); a.w = fmaxf(a.w, 0.f);
        ((float4*)&sh[(size_t)(tid >> 1) * NB])[half] = a;
        if (WRITEH && blockIdx.x == 0)
            ((float4*)(hOut + (size_t)jj * NB))[half] = a;
    }
    __syncthreads();
    // step B: MM chunk
    int j = blockIdx.x * 128 + tid;
    float acc[NB];
#pragma unroll
    for (int b = 0; b < NB; b++) acc[b] = 0.f;
    const float* Wp = W + (size_t)i0 * HD + j;
#pragma unroll 16
    for (int ii = 0; ii < 64; ii++) {
        float w = Wp[(size_t)ii * HD];
        const float4* h4 = (const float4*)&sh[ii * NB];
        float4 a = h4[0], c = h4[1];
        acc[0] += a.x * w; acc[1] += a.y * w; acc[2] += a.z * w; acc[3] += a.w * w;
        acc[4] += c.x * w; acc[5] += c.y * w; acc[6] += c.z * w; acc[7] += c.w * w;
    }
    float4* dst = (float4*)&partOut[((size_t)ch * HD + j) * NB];
    dst[0] = make_float4(acc[0], acc[1], acc[2], acc[3]);
    dst[1] = make_float4(acc[4], acc[5], acc[6], acc[7]);
}

// -------- fused: finalize h3 + coeff head split-K ---------------------------
__global__ void k_coeffF(const float* __restrict__ hResid,
                         const float* __restrict__ partIn,
                         const float* __restrict__ bias,
                         const float* __restrict__ Wx,
                         const float* __restrict__ Wy,
                         const float* __restrict__ Wz) {
    __shared__ __align__(16) float sh[64 * NB];
    int tid = threadIdx.x;                            // 320
    int ch = blockIdx.y;
    int i0 = ch * 64;
    if (tid < 128) {
        int jj = i0 + (tid >> 1);
        int half = tid & 1;
        float bb = bias[jj];
        float4 a = make_float4(bb, bb, bb, bb);
        float4 r = ((const float4*)(hResid + (size_t)jj * NB))[half];
        a.x += r.x; a.y += r.y; a.z += r.z; a.w += r.w;
#pragma unroll
        for (int c = 0; c < NCH_L; c++) {
            float4 p = ((const float4*)(partIn + ((size_t)c * HD + jj) * NB))[half];
            a.x += p.x; a.y += p.y; a.z += p.z; a.w += p.w;
        }
        a.x = fmaxf(a.x, 0.f); a.y = fmaxf(a.y, 0.f);
        a.z = fmaxf(a.z, 0.f); a.w = fmaxf(a.w, 0.f);
        ((float4*)&sh[(size_t)(tid >> 1) * NB])[half] = a;
    }
    __syncthreads();
    int k = tid;
    if (k >= KD) return;
    int axis = blockIdx.x;
    const float* W = (axis == 0) ? Wx : ((axis == 1) ? Wy : Wz);
    const float* Wp = W + (size_t)i0 * KD + k;
    float acc[NB];
#pragma unroll
    for (int b = 0; b < NB; b++) acc[b] = 0.f;
#pragma unroll 8
    for (int ii = 0; ii < 64; ii++) {
        float w = Wp[(size_t)ii * KD];
        const float4* h4 = (const float4*)&sh[ii * NB];
        float4 a = h4[0], c = h4[1];
        acc[0] += a.x * w; acc[1] += a.y * w; acc[2] += a.z * w; acc[3] += a.w * w;
        acc[4] += c.x * w; acc[5] += c.y * w; acc[6] += c.z * w; acc[7] += c.w * w;
    }
    float4* dst = (float4*)&g_cpart[(((size_t)axis * NCH_C + ch) * KD + k) * NB];
    dst[0] = make_float4(acc[0], acc[1], acc[2], acc[3]);
    dst[1] = make_float4(acc[4], acc[5], acc[6], acc[7]);
}

// epi: reduce chunks, write duplicated x64 pairs, block-reduce reg -> out
__global__ void k_coeff_epi(const float* __restrict__ bx,
                            const float* __restrict__ by,
                            const float* __restrict__ bz,
                            float* __restrict__ out, int do_write) {
    __shared__ float swarp[10];
    int k = threadIdx.x;
    float ss = 0.f;
    if (k < KD) {
#pragma unroll
        for (int axis = 0; axis < 3; axis++) {
            const float* bias = (axis == 0) ? bx : ((axis == 1) ? by : bz);
            float bb = bias[k];
            float acc[NB];
#pragma unroll
            for (int b = 0; b < NB; b++) acc[b] = bb;
#pragma unroll
            for (int c = 0; c < NCH_C; c++) {
                const float4* p = (const float4*)&g_cpart[(((size_t)axis * NCH_C + c) * KD + k) * NB];
                float4 a = p[0], d = p[1];
                acc[0] += a.x; acc[1] += a.y; acc[2] += a.z; acc[3] += a.w;
                acc[4] += d.x; acc[5] += d.y; acc[6] += d.z; acc[7] += d.w;
            }
#pragma unroll
            for (int b = 0; b < NB; b++) {
                float v = acc[b];
                ss += v * v;
                float sv = 64.f * v;
                g_cbuf2[k * 24 + b * 3 + axis] = make_float2(sv, sv);
            }
        }
    }
#pragma unroll
    for (int off = 16; off > 0; off >>= 1)
        ss += __shfl_down_sync(0xFFFFFFFFu, ss, off);
    if ((threadIdx.x & 31) == 0) swarp[threadIdx.x >> 5] = ss;
    __syncthreads();
    if (threadIdx.x == 0 && do_write) {
        float tot = 0.f;
#pragma unroll
        for (int w = 0; w < 10; w++) tot += swarp[w];
        out[(size_t)NB * ND * 3] = 1e-4f * sqrtf(tot);
    }
}

// -------- big GEMM: packed f32x2 FMA + 4-deep register prefetch -------------
__device__ __forceinline__ void gstep(unsigned long long* acc2,
                                      const unsigned long long* crow,
                                      unsigned long long zp0,
                                      unsigned long long zp1) {
    const ulonglong2* cr = (const ulonglong2*)crow;
#pragma unroll
    for (int q = 0; q < 12; q++) {
        ulonglong2 c = cr[q];
        int j0 = q * 2;
        asm("fma.rn.f32x2 %0, %1, %2, %0;" : "+l"(acc2[j0 * 2 + 0]) : "l"(c.x), "l"(zp0));
        asm("fma.rn.f32x2 %0, %1, %2, %0;" : "+l"(acc2[j0 * 2 + 1]) : "l"(c.x), "l"(zp1));
        asm("fma.rn.f32x2 %0, %1, %2, %0;" : "+l"(acc2[j0 * 2 + 2]) : "l"(c.y), "l"(zp0));
        asm("fma.rn.f32x2 %0, %1, %2, %0;" : "+l"(acc2[j0 * 2 + 3]) : "l"(c.y), "l"(zp1));
    }
}

__global__ __launch_bounds__(64) void k_gemm(const float* __restrict__ Z) {
    extern __shared__ __align__(16) unsigned long long cs[];  // KD*24 u64 pairs
    int tid = threadIdx.x;
    const ulonglong2* src = (const ulonglong2*)g_cbuf2;
    ulonglong2* d2 = (ulonglong2*)cs;
    for (int t = tid; t < KD * 12; t += 64) d2[t] = src[t];
    __syncthreads();
    int n = blockIdx.x * 256 + tid * 4;
    if (n >= ND) return;
    unsigned long long acc2[48];
#pragma unroll
    for (int t = 0; t < 48; t++) acc2[t] = 0ULL;
    const ulonglong2* Zp = (const ulonglong2*)(Z + n);
    const size_t str = ND / 4;
    ulonglong2 z0 = Zp[0], z1 = Zp[str], z2 = Zp[2 * str], z3 = Zp[3 * str];
#pragma unroll 1
    for (int k0 = 0; k0 < 285; k0 += 4) {
        ulonglong2 w0 = Zp[(size_t)(k0 + 4) * str];
        ulonglong2 w1 = Zp[(size_t)(k0 + 5) * str];
        ulonglong2 w2 = Zp[(size_t)(k0 + 6) * str];
        ulonglong2 w3 = Zp[(size_t)(k0 + 7) * str];
        gstep(acc2, cs + (size_t)(k0 + 0) * 24, z0.x, z0.y);
        gstep(acc2, cs + (size_t)(k0 + 1) * 24, z1.x, z1.y);
        gstep(acc2, cs + (size_t)(k0 + 2) * 24, z2.x, z2.y);
        gstep(acc2, cs + (size_t)(k0 + 3) * 24, z3.x, z3.y);
        z0 = w0; z1 = w1; z2 = w2; z3 = w3;
    }
    gstep(acc2, cs + 288 * 24, z0.x, z0.y);
    gstep(acc2, cs + 289 * 24, z1.x, z1.y);
    gstep(acc2, cs + 290 * 24, z2.x, z2.y);
    gstep(acc2, cs + 291 * 24, z3.x, z3.y);
    z0 = Zp[292 * str]; z1 = Zp[293 * str];
    gstep(acc2, cs + 292 * 24, z0.x, z0.y);
    gstep(acc2, cs + 293 * 24, z1.x, z1.y);

    float vals[96];
#pragma unroll
    for (int j = 0; j < 24; j++) {
#pragma unroll
        for (int p = 0; p < 2; p++) {
            float lo, hi;
            asm("mov.b64 {%0,%1}, %2;" : "=f"(lo), "=f"(hi) : "l"(acc2[j * 2 + p]));
            vals[j * 4 + 2 * p]     = lo;
            vals[j * 4 + 2 * p + 1] = hi;
        }
    }
#pragma unroll
    for (int comp = 0; comp < 4; comp++) {
        float4* out = (float4*)(g_f + (size_t)(n + comp) * 24);
#pragma unroll
        for (int q = 0; q < 6; q++)
            out[q] = make_float4(vals[(q * 4 + 0) * 4 + comp],
                                 vals[(q * 4 + 1) * 4 + comp],
                                 vals[(q * 4 + 2) * 4 + comp],
                                 vals[(q * 4 + 3) * 4 + comp]);
    }
}

// ---------------- CSR build (dtype detect folded into hist) -----------------
__global__ void k_hist(const int* __restrict__ ei32,
                       const float* __restrict__ ew) {
    __shared__ int s_is64;
    if (threadIdx.x == 0) {
        int z = ei32[1] | ei32[3] | ei32[5] | ei32[7];
        s_is64 = (z == 0) ? 1 : 0;
        if (blockIdx.x == 0) g_is64 = s_is64;
    }
    __syncthreads();
    int is64 = s_is64;
    int e = blockIdx.x * 256 + threadIdx.x;
    if (e >= ED) return;
    int d = load_ei(ei32, (size_t)ED + e, is64);
    if ((unsigned)d >= ND) return;
    atomicAdd(&g_cw[d], 1);
    atomicAdd((float*)&g_cw[ND + d], ew[e]);
}

__global__ void k_scan1() {                          // grid NSB, block 1024
    __shared__ int sred[32];
    int b = blockIdx.x, t = threadIdx.x;
    int idx = b * 1024 + t;
    int v = (idx < ND) ? g_cw[idx] : 0;
    int s = v;
#pragma unroll
    for (int off = 16; off > 0; off >>= 1)
        s += __shfl_down_sync(0xFFFFFFFFu, s, off);
    if ((t & 31) == 0) sred[t >> 5] = s;
    __syncthreads();
    if (t < 32) {
        int x = sred[t];
#pragma unroll
        for (int off = 16; off > 0; off >>= 1)
            x += __shfl_down_sync(0xFFFFFFFFu, x, off);
        if (t == 0) g_bsum[b] = x;
    }
}

__global__ void k_scan2() {                          // 1 block, 128 threads
    __shared__ int wsum[4];
    int t = threadIdx.x;
    int v = (t < NSB) ? g_bsum[t] : 0;
    int incl = v;
#pragma unroll
    for (int off = 1; off < 32; off <<= 1) {
        int x = __shfl_up_sync(0xFFFFFFFFu, incl, off);
        if ((t & 31) >= off) incl += x;
    }
    if ((t & 31) == 31) wsum[t >> 5] = incl;
    __syncthreads();
    int carry = 0;
    for (int w = 0; w < (t >> 5); w++) carry += wsum[w];
    incl += carry;
    if (t < NSB) g_boff[t] = incl - v;
    if (t == NSB - 1) g_rowptr[ND] = incl;
}

__global__ void k_scan3() {                          // grid NSB, block 1024
    __shared__ int sp[1024];
    int b = blockIdx.x, t = threadIdx.x;
    int idx = b * 1024 + t;
    int v = (idx < ND) ? g_cw[idx] : 0;
    sp[t] = v;
    __syncthreads();
    for (int off = 1; off < 1024; off <<= 1) {
        int x = (t >= off) ? sp[t - off] : 0;
        __syncthreads();
        sp[t] += x;
        __syncthreads();
    }
    if (idx < ND) {
        int excl = g_boff[b] + sp[t] - v;
        g_rowptr[idx] = excl;
        g_cursor[idx] = excl;
    }
}

__global__ void k_fill(const int* __restrict__ ei32,
                       const float* __restrict__ ew) {
    int e = blockIdx.x * 256 + threadIdx.x;
    if (e >= ED) return;
    int is64 = g_is64;
    int s = load_ei(ei32, (size_t)e, is64);
    int d = load_ei(ei32, (size_t)ED + e, is64);
    if ((unsigned)s >= ND || (unsigned)d >= ND) return;
    float wd = ((const float*)&g_cw[ND])[d];
    float wp = 0.5f * ew[e] / fmaxf(wd, 1e-6f);
    int slot = atomicAdd(&g_cursor[d], 1);
    g_recs[slot] = make_int2(s * 24, __float_as_int(wp));
}

// ---------------- diffusion: 2 threads per node, fused combine --------------
__global__ __launch_bounds__(256) void k_gather(const float* __restrict__ fin,
                                                float* __restrict__ fout) {
    int g = blockIdx.x * 256 + threadIdx.x;
    if (g >= 2 * ND) return;
    int n = g >> 1;
    int h = (g & 1) * 12;
    int beg = g_rowptr[n], end = g_rowptr[n + 1];
    float acc[12];
#pragma unroll
    for (int t = 0; t < 12; t++) acc[t] = 0.f;
    int i = beg;
    for (; i + 2 <= end; i += 2) {
        int2 r0 = g_recs[i], r1 = g_recs[i + 1];
        float w0 = __int_as_float(r0.y), w1 = __int_as_float(r1.y);
        const float4* a0 = (const float4*)(fin + r0.x + h);
        const float4* a1 = (const float4*)(fin + r1.x + h);
        float4 m0 = a0[0], m1 = a0[1], m2 = a0[2];
        float4 p0 = a1[0], p1 = a1[1], p2 = a1[2];
        acc[0] += m0.x * w0; acc[1] += m0.y * w0; acc[2]  += m0.z * w0; acc[3]  += m0.w * w0;
        acc[4] += m1.x * w0; acc[5] += m1.y * w0; acc[6]  += m1.z * w0; acc[7]  += m1.w * w0;
        acc[8] += m2.x * w0; acc[9] += m2.y * w0; acc[10] += m2.z * w0; acc[11] += m2.w * w0;
        acc[0] += p0.x * w1; acc[1] += p0.y * w1; acc[2]  += p0.z * w1; acc[3]  += p0.w * w1;
        acc[4] += p1.x * w1; acc[5] += p1.y * w1; acc[6]  += p1.z * w1; acc[7]  += p1.w * w1;
        acc[8] += p2.x * w1; acc[9] += p2.y * w1; acc[10] += p2.z * w1; acc[11] += p2.w * w1;
    }
    if (i < end) {
        int2 r0 = g_recs[i];
        float w0 = __int_as_float(r0.y);
        const float4* a0 = (const float4*)(fin + r0.x + h);
        float4 m0 = a0[0], m1 = a0[1], m2 = a0[2];
        acc[0] += m0.x * w0; acc[1] += m0.y * w0; acc[2]  += m0.z * w0; acc[3]  += m0.w * w0;
        acc[4] += m1.x * w0; acc[5] += m1.y * w0; acc[6]  += m1.z * w0; acc[7]  += m1.w * w0;
        acc[8] += m2.x * w0; acc[9] += m2.y * w0; acc[10] += m2.z * w0; acc[11] += m2.w * w0;
    }
    const float4* f0 = (const float4*)(fin + (size_t)n * 24 + h);
    float4* fo = (float4*)(fout + (size_t)n * 24 + h);
#pragma unroll
    for (int q = 0; q < 3; q++) {
        float4 f = f0[q];
        fo[q] = make_float4(0.5f * f.x + acc[q * 4 + 0],
                            0.5f * f.y + acc[q * 4 + 1],
                            0.5f * f.z + acc[q * 4 + 2],
                            0.5f * f.w + acc[q * 4 + 3]);
    }
}

// last step: gather + write directly to out in [b][n][3] layout
__global__ __launch_bounds__(256) void k_gather_out(const float* __restrict__ fin,
                                                    float* __restrict__ out) {
    int g = blockIdx.x * 256 + threadIdx.x;
    if (g >= 2 * ND) return;
    int n = g >> 1;
    int h = (g & 1) * 12;
    int beg = g_rowptr[n], end = g_rowptr[n + 1];
    float acc[12];
#pragma unroll
    for (int t = 0; t < 12; t++) acc[t] = 0.f;
    int i = beg;
    for (; i + 2 <= end; i += 2) {
        int2 r0 = g_recs[i], r1 = g_recs[i + 1];
        float w0 = __int_as_float(r0.y), w1 = __int_as_float(r1.y);
        const float4* a0 = (const float4*)(fin + r0.x + h);
        const float4* a1 = (const float4*)(fin + r1.x + h);
        float4 m0 = a0[0], m1 = a0[1], m2 = a0[2];
        float4 p0 = a1[0], p1 = a1[1], p2 = a1[2];
        acc[0] += m0.x * w0; acc[1] += m0.y * w0; acc[2]  += m0.z * w0; acc[3]  += m0.w * w0;
        acc[4] += m1.x * w0; acc[5] += m1.y * w0; acc[6]  += m1.z * w0; acc[7]  += m1.w * w0;
        acc[8] += m2.x * w0; acc[9] += m2.y * w0; acc[10] += m2.z * w0; acc[11] += m2.w * w0;
        acc[0] += p0.x * w1; acc[1] += p0.y * w1; acc[2]  += p0.z * w1; acc[3]  += p0.w * w1;
        acc[4] += p1.x * w1; acc[5] += p1.y * w1; acc[6]  += p1.z * w1; acc[7]  += p1.w * w1;
        acc[8] += p2.x * w1; acc[9] += p2.y * w1; acc[10] += p2.z * w1; acc[11] += p2.w * w1;
    }
    if (i < end) {
        int2 r0 = g_recs[i];
        float w0 = __int_as_float(r0.y);
        const float4* a0 = (const float4*)(fin + r0.x + h);
        float4 m0 = a0[0], m1 = a0[1], m2 = a0[2];
        acc[0] += m0.x * w0; acc[1] += m0.y * w0; acc[2]  += m0.z * w0; acc[3]  += m0.w * w0;
        acc[4] += m1.x * w0; acc[5] += m1.y * w0; acc[6]  += m1.z * w0; acc[7]  += m1.w * w0;
        acc[8] += m2.x * w0; acc[9] += m2.y * w0; acc[10] += m2.z * w0; acc[11] += m2.w * w0;
    }
    const float* f0 = fin + (size_t)n * 24 + h;
    int bbase = (h == 0) ? 0 : 4;
#pragma unroll
    for (int bb = 0; bb < 4; bb++) {
        float* op = out + (size_t)(bbase + bb) * (ND * 3) + (size_t)n * 3;
#pragma unroll
        for (int a = 0; a < 3; a++)
            op[a] = 0.5f * f0[bb * 3 + a] + acc[bb * 3 + a];
    }
}

// ---------------------------------------------------------------------------
extern "C" void kernel_launch(void* const* d_in, const int* in_sizes, int n_in,
                              void* d_out, int out_size) {
    const float* latent = (const float*)d_in[0];
    const float* W0 = (const float*)d_in[1];
    const float* b0 = (const float*)d_in[2];
    const float* W1 = (const float*)d_in[3];
    const float* b1 = (const float*)d_in[4];
    const float* W2 = (const float*)d_in[5];
    const float* b2 = (const float*)d_in[6];
    const float* W3 = (const float*)d_in[7];
    const float* b3 = (const float*)d_in[8];
    const float* Wx = (const float*)d_in[9];
    const float* bx = (const float*)d_in[10];
    const float* Wy = (const float*)d_in[11];
    const float* by = (const float*)d_in[12];
    const float* Wz = (const float*)d_in[13];
    const float* bz = (const float*)d_in[14];
    const float* Z  = (const float*)d_in[15];
    const float* ew = (const float*)d_in[16];
    const int*   ei = (const int*)d_in[17];   // int32 OR int64 (auto-detected)
    float* out = (float*)d_out;

    void *p_f, *p_fb, *p_cw, *p_hA, *p_hB, *p_pA, *p_pB;
    cudaGetSymbolAddress(&p_f, g_f);
    cudaGetSymbolAddress(&p_fb, g_fb);
    cudaGetSymbolAddress(&p_cw, g_cw);
    cudaGetSymbolAddress(&p_hA, g_hA);
    cudaGetSymbolAddress(&p_hB, g_hB);
    cudaGetSymbolAddress(&p_pA, g_partA);
    cudaGetSymbolAddress(&p_pB, g_partB);

    static cudaStream_t s2 = nullptr;
    static cudaEvent_t evFork = nullptr, evJoin = nullptr;
    if (!s2) {
        cudaStreamCreateWithFlags(&s2, cudaStreamNonBlocking);
        cudaEventCreateWithFlags(&evFork, cudaEventDisableTiming);
        cudaEventCreateWithFlags(&evJoin, cudaEventDisableTiming);
        cudaFuncSetAttribute(k_gemm, cudaFuncAttributeMaxDynamicSharedMemorySize,
                             KD * 24 * 8);
    }

    // ---- fork: CSR build on s2, MLP+GEMM on capture stream -----------------
    cudaEventRecord(evFork, 0);
    cudaStreamWaitEvent(s2, evFork, 0);

    cudaMemsetAsync(p_cw, 0, (size_t)2 * ND * sizeof(int), s2);
    k_hist<<<(ED + 255) / 256, 256, 0, s2>>>(ei, ew);
    k_scan1<<<NSB, 1024, 0, s2>>>();
    k_scan2<<<1, 128, 0, s2>>>();
    k_scan3<<<NSB, 1024, 0, s2>>>();
    k_fill<<<(ED + 255) / 256, 256, 0, s2>>>(ei, ew);
    cudaEventRecord(evJoin, s2);

    // MLP decode: fused finalize+MM chain
    k_mlp0_splitK<<<dim3(8, NCH_0), 128>>>(latent, W0);                       // -> partA
    k_layerF<NCH_0, false, true><<<dim3(8, NCH_L), 128>>>(                    // h0, W1 -> partB
        nullptr, (float*)p_pA, (float*)p_pB, (float*)p_hA, b0, W1);
    k_layerF<NCH_L, true, true><<<dim3(8, NCH_L), 128>>>(                     // h1, W2 -> partA
        (float*)p_hA, (float*)p_pB, (float*)p_pA, (float*)p_hB, b1, W2);
    k_layerF<NCH_L, true, true><<<dim3(8, NCH_L), 128>>>(                     // h2, W3 -> partB
        (float*)p_hB, (float*)p_pA, (float*)p_pB, (float*)p_hA, b2, W3);
    k_coeffF<<<dim3(3, NCH_C), 320>>>(                                        // h3, coeff heads
        (float*)p_hA, (float*)p_pB, b3, Wx, Wy, Wz);
    k_coeff_epi<<<1, 320>>>(bx, by, bz, out, (out_size > NB * ND * 3) ? 1 : 0);

    // dense projection onto basis Z (packed f32x2 FMA, pipelined)
    k_gemm<<<(ND + 255) / 256, 64, KD * 24 * 8>>>(Z);

    // ---- join: diffusion needs both GEMM (this stream) and CSR (s2) --------
    cudaStreamWaitEvent(0, evJoin, 0);

    k_gather<<<(2 * ND + 255) / 256, 256>>>((float*)p_f,  (float*)p_fb);
    k_gather<<<(2 * ND + 255) / 256, 256>>>((float*)p_fb, (float*)p_f);
    k_gather_out<<<(2 * ND + 255) / 256, 256>>>((float*)p_f, out);
}